// round 7
// baseline (speedup 1.0000x reference)
#include <cuda_runtime.h>
#include <cuda_fp16.h>
#include <stdint.h>
#include <math.h>

// Problem dims
#define S_TOT 4096     // BS*N
#define D_DIM 1024
#define T_DIM 2048
#define V_DIM 32000
#define NB 8

// Scratch (device globals — allocation-free rule)
__device__ float g_x[S_TOT * D_DIM];
__device__ float g_xb[S_TOT * T_DIM];
__device__ float g_zhat[S_TOT * NB * 64];
__device__ float g_pcm[2 * S_TOT * NB];
__device__ __half g_Ah[(size_t)S_TOT * 2048];
__device__ __half g_Bh[(size_t)V_DIM * 1024];
__device__ __half g_Axo[(size_t)S_TOT * 3072];
__device__ __half g_Bfo[(size_t)T_DIM * 3072];
__device__ __half g_Axi[(size_t)S_TOT * 6144];
__device__ __half g_Bfi[(size_t)D_DIM * 6144];
__device__ __half g_W1p[NB * 256 * 64];
__device__ __half g_W2p[NB * 64 * 256];

__device__ __forceinline__ uint32_t smem_u32(const void* p) {
    uint32_t a;
    asm("{ .reg .u64 t; cvta.to.shared.u64 t, %1; cvt.u32.u64 %0, t; }"
        : "=r"(a) : "l"(p));
    return a;
}
__device__ __forceinline__ void ldsm4(uint32_t* r, uint32_t addr) {
    asm volatile("ldmatrix.sync.aligned.m8n8.x4.shared.b16 {%0,%1,%2,%3}, [%4];"
                 : "=r"(r[0]), "=r"(r[1]), "=r"(r[2]), "=r"(r[3]) : "r"(addr));
}
__device__ __forceinline__ void mma16816(float* c, const uint32_t* a,
                                         uint32_t b0, uint32_t b1) {
    asm volatile(
        "mma.sync.aligned.m16n8k16.row.col.f32.f16.f16.f32 "
        "{%0,%1,%2,%3}, {%4,%5,%6,%7}, {%8,%9}, {%0,%1,%2,%3};"
        : "+f"(c[0]), "+f"(c[1]), "+f"(c[2]), "+f"(c[3])
        : "r"(a[0]), "r"(a[1]), "r"(a[2]), "r"(a[3]), "r"(b0), "r"(b1));
}
__device__ __forceinline__ float gelu_f(float v) {
    float u = 0.7978845608028654f * (v + 0.044715f * v * v * v);
    float th;
    asm("tanh.approx.f32 %0, %1;" : "=f"(th) : "f"(u));
    return 0.5f * v * (1.0f + th);
}
__device__ __forceinline__ uint32_t pack_h2(float a, float b) {
    __half ha = __float2half_rn(a), hb = __float2half_rn(b);
    return (uint32_t)__half_as_ushort(ha) | ((uint32_t)__half_as_ushort(hb) << 16);
}

// ---------------------------------------------------------------------------
// Conversions
// ---------------------------------------------------------------------------
__global__ void convA_h(const float* __restrict__ x, __half* __restrict__ Ah) {
    int row = blockIdx.x;
    int q = threadIdx.x;
    float4 v = ((const float4*)(x + (size_t)row * 1024))[q];
    __half h0 = __float2half_rn(v.x), h1 = __float2half_rn(v.y);
    __half h2 = __float2half_rn(v.z), h3 = __float2half_rn(v.w);
    uint2 H, L;
    H.x = pack_h2(v.x, v.y); H.y = pack_h2(v.z, v.w);
    L.x = pack_h2(v.x - __half2float(h0), v.y - __half2float(h1));
    L.y = pack_h2(v.z - __half2float(h2), v.w - __half2float(h3));
    __half* base = Ah + (size_t)row * 2048 + q * 4;
    *(uint2*)base = H;
    *(uint2*)(base + 1024) = L;
}

__global__ void convB_h(const float* __restrict__ emb, __half* __restrict__ Bh) {
    size_t i = (size_t)blockIdx.x * 256 + threadIdx.x;
    float4 v = ((const float4*)emb)[i];
    uint2 H;
    H.x = pack_h2(v.x, v.y); H.y = pack_h2(v.z, v.w);
    ((uint2*)Bh)[i] = H;
}

__global__ void convA3(const float* __restrict__ src, __half* __restrict__ dst,
                       int K) {
    int row = blockIdx.x;
    const float4* sp = (const float4*)(src + (size_t)row * K);
    __half* base = dst + (size_t)row * 3 * K;
    for (int q = threadIdx.x; q < K / 4; q += 256) {
        float4 v = sp[q];
        __half h0 = __float2half_rn(v.x), h1 = __float2half_rn(v.y);
        __half h2 = __float2half_rn(v.z), h3 = __float2half_rn(v.w);
        uint2 H, L;
        H.x = pack_h2(v.x, v.y); H.y = pack_h2(v.z, v.w);
        L.x = pack_h2(v.x - __half2float(h0), v.y - __half2float(h1));
        L.y = pack_h2(v.z - __half2float(h2), v.w - __half2float(h3));
        *(uint2*)(base + q * 4)         = H;
        *(uint2*)(base + K + q * 4)     = L;
        *(uint2*)(base + 2 * K + q * 4) = H;
    }
}

__global__ void convB3T(const float* __restrict__ src, __half* __restrict__ dst,
                        int K, int N) {
    __shared__ float tile[32][33];
    int k0 = blockIdx.x * 32, n0 = blockIdx.y * 32;
    int tx = threadIdx.x & 31, ty = threadIdx.x >> 5;
    for (int i = ty; i < 32; i += 8)
        tile[i][tx] = src[(size_t)(k0 + i) * N + n0 + tx];
    __syncthreads();
    for (int i = ty; i < 32; i += 8) {
        int n = n0 + i;
        float v = tile[tx][i];
        __half h = __float2half_rn(v);
        __half l = __float2half_rn(v - __half2float(h));
        __half* row = dst + (size_t)n * 3 * K + k0 + tx;
        row[0]     = h;
        row[K]     = h;
        row[2 * K] = l;
    }
}

// Pre-swizzled fp16 weights for mlp_tc
__global__ void convW1p(const float* __restrict__ W1, __half* __restrict__ W1p) {
    int idx = blockIdx.x * 256 + threadIdx.x;
    int t = idx >> 14, rem = idx & 16383;
    int rr = rem >> 6, ph = (rem >> 3) & 7, j = rem & 7;
    int k = ((ph ^ (rr & 7)) << 3) | j;
    W1p[idx] = __float2half_rn(W1[((size_t)t * 64 + k) * 256 + rr]);
}
__global__ void convW2p(const float* __restrict__ W2, __half* __restrict__ W2p) {
    int idx = blockIdx.x * 256 + threadIdx.x;
    int t = idx >> 14, rem = idx & 16383;
    int rr = rem >> 8, ph = (rem >> 3) & 31, j = rem & 7;
    int c = (ph & ~7) | ((ph & 7) ^ (rr & 7));
    int k = (c << 3) | j;
    W2p[idx] = __float2half_rn(W2[((size_t)t * 256 + k) * 64 + rr]);
}

// ---------------------------------------------------------------------------
// HMMA fp16 GEMM, 128x128 tile (fan_out / fan_in)
// ---------------------------------------------------------------------------
#define HBUF 32768
#define HSMEM (2 * HBUF)

__global__ __launch_bounds__(256) void gemm_hmma(
    const __half* __restrict__ A, const __half* __restrict__ B,
    const float* __restrict__ bias, float* __restrict__ C,
    int ldA, int ldB, int N, int nch, int bkmask) {
    extern __shared__ __align__(128) char smem[];
    const uint32_t sb = smem_u32(smem);
    const int tid = threadIdx.x, lane = tid & 31, wid = tid >> 5;
    const int bm = blockIdx.x * 128, bn = blockIdx.y * 128;
    const int wm = (wid & 1) * 64, wn = (wid >> 1) * 32;

    float acc[4][4][4] = {};

    auto issue = [&](int ch, int buf) {
        int k0 = ch * 64;
        int bk = k0 & bkmask;
        uint32_t abase = sb + buf * HBUF;
        uint32_t bbase = abase + 16384;
#pragma unroll
        for (int i = 0; i < 4; i++) {
            int idx = tid + 256 * i;
            int r = idx >> 3, c = idx & 7;
            uint32_t off = (uint32_t)(r * 128 + ((c ^ (r & 7)) * 16));
            const __half* gp = A + (size_t)(bm + r) * ldA + k0 + c * 8;
            asm volatile("cp.async.cg.shared.global [%0], [%1], 16;"
                         :: "r"(abase + off), "l"(gp));
        }
#pragma unroll
        for (int i = 0; i < 4; i++) {
            int idx = tid + 256 * i;
            int r = idx >> 3, c = idx & 7;
            uint32_t off = (uint32_t)(r * 128 + ((c ^ (r & 7)) * 16));
            const __half* gp = B + (size_t)(bn + r) * ldB + bk + c * 8;
            asm volatile("cp.async.cg.shared.global [%0], [%1], 16;"
                         :: "r"(bbase + off), "l"(gp));
        }
        asm volatile("cp.async.commit_group;" ::: "memory");
    };

    issue(0, 0);

    for (int ch = 0; ch < nch; ch++) {
        int b = ch & 1;
        if (ch + 1 < nch) {
            issue(ch + 1, b ^ 1);
            asm volatile("cp.async.wait_group 1;" ::: "memory");
        } else {
            asm volatile("cp.async.wait_group 0;" ::: "memory");
        }
        __syncthreads();

        uint32_t abase = sb + b * HBUF;
        uint32_t bbase = abase + 16384;
#pragma unroll
        for (int ks = 0; ks < 4; ks++) {
            uint32_t afr[4][4];
#pragma unroll
            for (int mi = 0; mi < 4; mi++) {
                int r = wm + mi * 16 + (lane & 15);
                int cu = ks * 2 + (lane >> 4);
                uint32_t addr = abase + r * 128 + ((cu ^ (r & 7)) * 16);
                ldsm4(afr[mi], addr);
            }
            uint32_t bfr[2][4];
#pragma unroll
            for (int p = 0; p < 2; p++) {
                int r = wn + p * 16 + (lane & 7) + ((lane >> 4) * 8);
                int cu = ks * 2 + ((lane >> 3) & 1);
                uint32_t addr = bbase + r * 128 + ((cu ^ (r & 7)) * 16);
                ldsm4(bfr[p], addr);
            }
#pragma unroll
            for (int mi = 0; mi < 4; mi++)
#pragma unroll
                for (int nj = 0; nj < 4; nj++)
                    mma16816(acc[mi][nj], afr[mi],
                             bfr[nj >> 1][(nj & 1) * 2 + 0],
                             bfr[nj >> 1][(nj & 1) * 2 + 1]);
        }
        __syncthreads();
    }

#pragma unroll
    for (int mi = 0; mi < 4; mi++) {
#pragma unroll
        for (int nj = 0; nj < 4; nj++) {
            int row = bm + wm + mi * 16 + (lane >> 2);
            int col = bn + wn + nj * 8 + (lane & 3) * 2;
            float b0 = bias ? bias[col] : 0.0f;
            float b1 = bias ? bias[col + 1] : 0.0f;
            float2 v0 = make_float2(acc[mi][nj][0] + b0, acc[mi][nj][1] + b1);
            float2 v1 = make_float2(acc[mi][nj][2] + b0, acc[mi][nj][3] + b1);
            *(float2*)(C + (size_t)row * N + col) = v0;
            *(float2*)(C + (size_t)(row + 8) * N + col) = v1;
        }
    }
}

// ---------------------------------------------------------------------------
// HMMA fp16 GEMM, 128x256 tile (logits). A[4096,2048] 2-term, B wrap 1024.
// 8 warps, warp tile 64x64. Per buffer: A 16KB + B 32KB.
// ---------------------------------------------------------------------------
#define G256BUF 49152
#define G256_SMEM (2 * G256BUF)
__global__ __launch_bounds__(256) void gemm_hmma_n256(
    const __half* __restrict__ A, const __half* __restrict__ B,
    float* __restrict__ C) {
    extern __shared__ __align__(128) char smem[];
    const uint32_t sb = smem_u32(smem);
    const int tid = threadIdx.x, lane = tid & 31, wid = tid >> 5;
    const int bm = blockIdx.x * 128, bn = blockIdx.y * 256;
    const int wm = (wid & 1) * 64, wn = (wid >> 1) * 64;

    float acc[4][8][4] = {};

    auto issue = [&](int ch, int buf) {
        int k0 = ch * 64;
        int bk = k0 & 1023;
        uint32_t abase = sb + buf * G256BUF;
        uint32_t bbase = abase + 16384;
#pragma unroll
        for (int i = 0; i < 4; i++) {
            int idx = tid + 256 * i;
            int r = idx >> 3, c = idx & 7;
            uint32_t off = (uint32_t)(r * 128 + ((c ^ (r & 7)) * 16));
            const __half* gp = A + (size_t)(bm + r) * 2048 + k0 + c * 8;
            asm volatile("cp.async.cg.shared.global [%0], [%1], 16;"
                         :: "r"(abase + off), "l"(gp));
        }
#pragma unroll
        for (int i = 0; i < 8; i++) {
            int idx = tid + 256 * i;
            int r = idx >> 3, c = idx & 7;
            uint32_t off = (uint32_t)(r * 128 + ((c ^ (r & 7)) * 16));
            const __half* gp = B + (size_t)(bn + r) * 1024 + bk + c * 8;
            asm volatile("cp.async.cg.shared.global [%0], [%1], 16;"
                         :: "r"(bbase + off), "l"(gp));
        }
        asm volatile("cp.async.commit_group;" ::: "memory");
    };

    issue(0, 0);

    const int NCH = 32;
    for (int ch = 0; ch < NCH; ch++) {
        int b = ch & 1;
        if (ch + 1 < NCH) {
            issue(ch + 1, b ^ 1);
            asm volatile("cp.async.wait_group 1;" ::: "memory");
        } else {
            asm volatile("cp.async.wait_group 0;" ::: "memory");
        }
        __syncthreads();

        uint32_t abase = sb + b * G256BUF;
        uint32_t bbase = abase + 16384;
#pragma unroll
        for (int ks = 0; ks < 4; ks++) {
            uint32_t afr[4][4];
#pragma unroll
            for (int mi = 0; mi < 4; mi++) {
                int r = wm + mi * 16 + (lane & 15);
                int cu = ks * 2 + (lane >> 4);
                ldsm4(afr[mi], abase + r * 128 + ((cu ^ (r & 7)) * 16));
            }
            uint32_t bfr[4][4];
#pragma unroll
            for (int p = 0; p < 4; p++) {
                int r = wn + p * 16 + (lane & 7) + ((lane >> 4) * 8);
                int cu = ks * 2 + ((lane >> 3) & 1);
                ldsm4(bfr[p], bbase + r * 128 + ((cu ^ (r & 7)) * 16));
            }
#pragma unroll
            for (int mi = 0; mi < 4; mi++)
#pragma unroll
                for (int nj = 0; nj < 8; nj++)
                    mma16816(acc[mi][nj], afr[mi],
                             bfr[nj >> 1][(nj & 1) * 2 + 0],
                             bfr[nj >> 1][(nj & 1) * 2 + 1]);
        }
        __syncthreads();
    }

#pragma unroll
    for (int mi = 0; mi < 4; mi++) {
#pragma unroll
        for (int nj = 0; nj < 8; nj++) {
            int row = bm + wm + mi * 16 + (lane >> 2);
            int col = bn + wn + nj * 8 + (lane & 3) * 2;
            float2 v0 = make_float2(acc[mi][nj][0], acc[mi][nj][1]);
            float2 v1 = make_float2(acc[mi][nj][2], acc[mi][nj][3]);
            *(float2*)(C + (size_t)row * V_DIM + col) = v0;
            *(float2*)(C + (size_t)(row + 8) * V_DIM + col) = v1;
        }
    }
}

// ---------------------------------------------------------------------------
// Fused HMMA refine MLP + z-pass.
// CTA = 128 tile rows x one block t (= 32 full (s,t) groups).
// Steps: load X (split fp16) -> z = mean_c -> pcm + zhat (fp32 matvec vs Wz)
//        -> phase1 H=gelu(X2@W1h) -> phase2 delta=H2@W2h -> xb += lam*delta.
// Smem: XS 0..32K, W1S 32..64K (phase1); HS 0..128K (phase2); W2S 128..160K;
//       WZS 160..176K (fp32 Wz[t]); ZS 176..184K (fp32 z[32][64]).
// ---------------------------------------------------------------------------
#define MLPTC_SMEM (163840 + 16384 + 8192)
__global__ __launch_bounds__(256) void mlp_tc(
    float* __restrict__ xb, const __half* __restrict__ W1p,
    const __half* __restrict__ W2p, const float* __restrict__ Wz,
    float* __restrict__ zhat, float* __restrict__ pcm,
    const float* __restrict__ lam_logit, int r) {
    extern __shared__ __align__(128) char smem[];
    const uint32_t sb = smem_u32(smem);
    const uint32_t XS = sb, W1S = sb + 32768, HS = sb, W2S = sb + 131072;
    const uint32_t WZS = sb + 163840;
    float* zsp = (float*)(smem + 180224);
    float* wzsp = (float*)(smem + 163840);
    const int tid = threadIdx.x, lane = tid & 31, wid = tid >> 5;
    const int t = blockIdx.y, rt = blockIdx.x;
    const int wm = (wid & 1) * 64;
    float lam = 1.0f;
    if (r > 0) lam = 1.0f / (1.0f + expf(-lam_logit[0]));

    // async-load weights: W1p, W2p (pre-swizzled fp16), Wz (fp32)
    {
        const __half* w1g = W1p + (size_t)t * 16384;
        const __half* w2g = W2p + (size_t)t * 16384;
        const float* wzg = Wz + (size_t)t * 4096;
#pragma unroll
        for (int i = 0; i < 8; i++) {
            int idx = tid + 256 * i;
            asm volatile("cp.async.cg.shared.global [%0], [%1], 16;"
                         :: "r"(W1S + idx * 16), "l"(w1g + idx * 8));
        }
#pragma unroll
        for (int i = 0; i < 8; i++) {
            int idx = tid + 256 * i;
            asm volatile("cp.async.cg.shared.global [%0], [%1], 16;"
                         :: "r"(W2S + idx * 16), "l"(w2g + idx * 8));
        }
#pragma unroll
        for (int i = 0; i < 4; i++) {
            int idx = tid + 256 * i;
            asm volatile("cp.async.cg.shared.global [%0], [%1], 16;"
                         :: "r"(WZS + idx * 16), "l"(wzg + idx * 4));
        }
        asm volatile("cp.async.commit_group;" ::: "memory");
    }

    // X tile: load fp32, split hi/lo fp16 into XS (row stride 256B, swizzled)
#pragma unroll
    for (int i = 0; i < 4; i++) {
        int idx = tid + 256 * i;
        int lr = idx >> 3, c = idx & 7;
        int g = rt * 128 + lr;
        const float* xp = xb + ((size_t)(g >> 2) * 32 + t * 4 + (g & 3)) * 64 + c * 8;
        float4 v0 = *(const float4*)xp;
        float4 v1 = *(const float4*)(xp + 4);
        float vv[8] = {v0.x, v0.y, v0.z, v0.w, v1.x, v1.y, v1.z, v1.w};
        uint4 Hh, Ll;
        uint32_t* hw = (uint32_t*)&Hh;
        uint32_t* lw = (uint32_t*)&Ll;
#pragma unroll
        for (int j = 0; j < 4; j++) {
            float a = vv[2 * j], b = vv[2 * j + 1];
            __half ha = __float2half_rn(a), hb = __float2half_rn(b);
            hw[j] = (uint32_t)__half_as_ushort(ha) |
                    ((uint32_t)__half_as_ushort(hb) << 16);
            lw[j] = pack_h2(a - __half2float(ha), b - __half2float(hb));
        }
        int phh = c ^ (lr & 7);
        *(uint4*)(smem + lr * 256 + phh * 16) = Hh;
        *(uint4*)(smem + lr * 256 + (8 + phh) * 16) = Ll;
    }
    __syncthreads();  // XS visible

    // z = mean_c (hi+lo reconstruction ~fp32-exact)
    {
        int s_loc = tid >> 3;
        int d0 = (tid & 7) * 8;
        float zv[8] = {};
#pragma unroll
        for (int c = 0; c < 4; c++) {
            int lr = s_loc * 4 + c;
            int byte_off = lr * 256 + (((d0 >> 3) ^ (lr & 7)) * 16);
            uint4 hi = *(const uint4*)(smem + byte_off);
            uint4 lo = *(const uint4*)(smem + byte_off + 128);
            const __half2* hp = (const __half2*)&hi;
            const __half2* lp = (const __half2*)&lo;
#pragma unroll
            for (int j = 0; j < 4; j++) {
                float2 h2 = __half22float2(hp[j]);
                float2 l2 = __half22float2(lp[j]);
                zv[2 * j]     += h2.x + l2.x;
                zv[2 * j + 1] += h2.y + l2.y;
            }
        }
#pragma unroll
        for (int j = 0; j < 8; j++) zsp[s_loc * 64 + d0 + j] = 0.25f * zv[j];
    }
    asm volatile("cp.async.wait_group 0;" ::: "memory");  // weights in
    __syncthreads();  // ZS + weights visible

    // pcm (r>0) + zhat = z @ Wz[t]
    {
        int s_loc = tid >> 3, e0 = (tid & 7) * 8;
        int st = (rt * 32 + s_loc) * 8 + t;
        const float* zr = zsp + s_loc * 64;
        float acc[8] = {};
        for (int d = 0; d < 64; d++) {
            float zv = zr[d];
            const float* wr = wzsp + d * 64 + e0;
#pragma unroll
            for (int j = 0; j < 8; j++) acc[j] = fmaf(zv, wr[j], acc[j]);
        }
        if (r > 0) {
            float sq = 0.0f;
#pragma unroll
            for (int j = 0; j < 8; j++) {
                float diff = zhat[(size_t)st * 64 + e0 + j] - zr[e0 + j];
                sq = fmaf(diff, diff, sq);
            }
            sq += __shfl_down_sync(0xffffffffu, sq, 4, 8);
            sq += __shfl_down_sync(0xffffffffu, sq, 2, 8);
            sq += __shfl_down_sync(0xffffffffu, sq, 1, 8);
            if ((tid & 7) == 0)
                pcm[(size_t)(r - 1) * (S_TOT * NB) + st] = sq;
        }
#pragma unroll
        for (int j = 0; j < 8; j++) zhat[(size_t)st * 64 + e0 + j] = acc[j];
    }

    // Phase 1: H[128x256] = gelu(X2 @ W1h), warp tile 64x64
    float acc1[4][8][4] = {};
    {
        const int wn1 = (wid >> 1) * 64;
#pragma unroll
        for (int ks = 0; ks < 8; ks++) {
            uint32_t afr[4][4];
#pragma unroll
            for (int mi = 0; mi < 4; mi++) {
                int rr = wm + mi * 16 + (lane & 15);
                int cu = ks * 2 + (lane >> 4);
                int ph = (cu & 8) | ((cu & 7) ^ (rr & 7));
                ldsm4(afr[mi], XS + rr * 256 + ph * 16);
            }
            uint32_t bfr[4][4];
#pragma unroll
            for (int p = 0; p < 4; p++) {
                int rr = wn1 + p * 16 + (lane & 7) + ((lane >> 4) * 8);
                int cu = (ks * 2 + ((lane >> 3) & 1)) & 7;
                int ph = cu ^ (rr & 7);
                ldsm4(bfr[p], W1S + rr * 128 + ph * 16);
            }
#pragma unroll
            for (int mi = 0; mi < 4; mi++)
#pragma unroll
                for (int nj = 0; nj < 8; nj++)
                    mma16816(acc1[mi][nj], afr[mi],
                             bfr[nj >> 1][(nj & 1) * 2 + 0],
                             bfr[nj >> 1][(nj & 1) * 2 + 1]);
        }
        __syncthreads();  // phase1 smem reads done (XS/W1S free)

        const int wn1b = (wid >> 1) * 64;
#pragma unroll
        for (int mi = 0; mi < 4; mi++)
#pragma unroll
            for (int nj = 0; nj < 8; nj++) {
                int r0 = wm + mi * 16 + (lane >> 2);
                int n0 = wn1b + nj * 8 + (lane & 3) * 2;
                float g0 = gelu_f(acc1[mi][nj][0]);
                float g1 = gelu_f(acc1[mi][nj][1]);
                float g2 = gelu_f(acc1[mi][nj][2]);
                float g3 = gelu_f(acc1[mi][nj][3]);
                __half h0 = __float2half_rn(g0), h1 = __float2half_rn(g1);
                __half h2 = __float2half_rn(g2), h3 = __float2half_rn(g3);
                uint32_t hi0 = (uint32_t)__half_as_ushort(h0) |
                               ((uint32_t)__half_as_ushort(h1) << 16);
                uint32_t hi1 = (uint32_t)__half_as_ushort(h2) |
                               ((uint32_t)__half_as_ushort(h3) << 16);
                uint32_t lo0 = pack_h2(g0 - __half2float(h0), g1 - __half2float(h1));
                uint32_t lo1 = pack_h2(g2 - __half2float(h2), g3 - __half2float(h3));
                int ch = n0 >> 3, within = (n0 & 7) * 2;
                int ph = (ch & ~7) | ((ch & 7) ^ (r0 & 7));
                char* base0 = smem + r0 * 1024 + within;
                char* base1 = smem + (r0 + 8) * 1024 + within;
                *(uint32_t*)(base0 + ph * 16) = hi0;
                *(uint32_t*)(base0 + (ph + 32) * 16) = lo0;
                *(uint32_t*)(base1 + ph * 16) = hi1;
                *(uint32_t*)(base1 + (ph + 32) * 16) = lo1;
            }
    }
    __syncthreads();

    // Phase 2: delta[128x64], warp tile 64x16, K'=512
    float acc2[4][2][4] = {};
    const int wn2 = (wid >> 1) * 16;
#pragma unroll
    for (int ks = 0; ks < 32; ks++) {
        uint32_t afr[4][4];
#pragma unroll
        for (int mi = 0; mi < 4; mi++) {
            int rr = wm + mi * 16 + (lane & 15);
            int cu = ks * 2 + (lane >> 4);
            int ph = (cu & ~7) | ((cu & 7) ^ (rr & 7));
            ldsm4(afr[mi], HS + rr * 1024 + ph * 16);
        }
        uint32_t bfr[4];
        {
            int rr = wn2 + (lane & 7) + ((lane >> 4) * 8);
            int cu = (ks * 2 + ((lane >> 3) & 1)) & 31;
            int ph = (cu & ~7) | ((cu & 7) ^ (rr & 7));
            ldsm4(bfr, W2S + rr * 512 + ph * 16);
        }
#pragma unroll
        for (int mi = 0; mi < 4; mi++)
#pragma unroll
            for (int nj = 0; nj < 2; nj++)
                mma16816(acc2[mi][nj], afr[mi], bfr[nj * 2], bfr[nj * 2 + 1]);
    }

    // Epilogue: xb += lam * delta
#pragma unroll
    for (int mi = 0; mi < 4; mi++)
#pragma unroll
        for (int nj = 0; nj < 2; nj++) {
            int r0 = wm + mi * 16 + (lane >> 2);
            int n0 = wn2 + nj * 8 + (lane & 3) * 2;
#pragma unroll
            for (int h = 0; h < 2; h++) {
                int g = rt * 128 + r0 + h * 8;
                float* p = xb + ((size_t)(g >> 2) * 32 + t * 4 + (g & 3)) * 64 + n0;
                float2 old = *(float2*)p;
                old.x += lam * acc2[mi][nj][h * 2 + 0];
                old.y += lam * acc2[mi][nj][h * 2 + 1];
                *(float2*)p = old;
            }
        }
}

// ---------------------------------------------------------------------------
// Embedding gather + pos add
// ---------------------------------------------------------------------------
__global__ void embed_kernel(const int* __restrict__ ids,
                             const float* __restrict__ emb,
                             const float* __restrict__ pos,
                             float* __restrict__ x) {
    int s = blockIdx.x;
    int q = threadIdx.x;
    int id = ids[s];
    float4 e = ((const float4*)(emb + (size_t)id * D_DIM))[q];
    float4 p = ((const float4*)(pos + (size_t)(s & 1023) * D_DIM))[q];
    float4 o;
    o.x = e.x + p.x; o.y = e.y + p.y; o.z = e.z + p.z; o.w = e.w + p.w;
    ((float4*)(x + (size_t)s * D_DIM))[q] = o;
}

// ---------------------------------------------------------------------------
// LayerNorm (in place)
// ---------------------------------------------------------------------------
__global__ void ln_kernel(float* __restrict__ x, const float* __restrict__ g,
                          const float* __restrict__ b) {
    __shared__ float red[256];
    const int s = blockIdx.x, tid = threadIdx.x;
    float4* row = (float4*)(x + (size_t)s * D_DIM);
    float4 v = row[tid];
    red[tid] = v.x + v.y + v.z + v.w;
    __syncthreads();
    for (int o = 128; o > 0; o >>= 1) {
        if (tid < o) red[tid] += red[tid + o];
        __syncthreads();
    }
    float mu = red[0] * (1.0f / 1024.0f);
    __syncthreads();
    float dx = v.x - mu, dy = v.y - mu, dz = v.z - mu, dw = v.w - mu;
    red[tid] = dx * dx + dy * dy + dz * dz + dw * dw;
    __syncthreads();
    for (int o = 128; o > 0; o >>= 1) {
        if (tid < o) red[tid] += red[tid + o];
        __syncthreads();
    }
    float rstd = rsqrtf(red[0] * (1.0f / 1024.0f) + 1e-5f);
    float4 gg = ((const float4*)g)[tid];
    float4 bb = ((const float4*)b)[tid];
    float4 o4;
    o4.x = dx * rstd * gg.x + bb.x;
    o4.y = dy * rstd * gg.y + bb.y;
    o4.z = dz * rstd * gg.z + bb.z;
    o4.w = dw * rstd * gg.w + bb.w;
    row[tid] = o4;
}

// ---------------------------------------------------------------------------
// Deterministic aux reduction
// ---------------------------------------------------------------------------
__global__ void aux_kernel(const float* __restrict__ pcm, float* __restrict__ out) {
    __shared__ float red[256];
    const int tid = threadIdx.x;
    float s = 0.0f;
    for (int i = tid; i < 2 * S_TOT * NB; i += 256) s += pcm[i];
    red[tid] = s;
    __syncthreads();
    for (int o = 128; o > 0; o >>= 1) {
        if (tid < o) red[tid] += red[tid + o];
        __syncthreads();
    }
    if (tid == 0) out[0] = 0.1f * red[0] / 262144.0f;
}

// ---------------------------------------------------------------------------
extern "C" void kernel_launch(void* const* d_in, const int* in_sizes, int n_in,
                              void* d_out, int out_size) {
    const int*   ids  = (const int*)d_in[0];
    const float* emb  = (const float*)d_in[1];
    const float* pos  = (const float*)d_in[2];
    const float* fo_w = (const float*)d_in[3];
    const float* fo_b = (const float*)d_in[4];
    const float* W1   = (const float*)d_in[5];
    const float* W2   = (const float*)d_in[6];
    const float* Wz   = (const float*)d_in[7];
    const float* fi_w = (const float*)d_in[8];
    const float* fi_b = (const float*)d_in[9];
    const float* ln_g = (const float*)d_in[10];
    const float* ln_b = (const float*)d_in[11];
    const float* lamp = (const float*)d_in[12];
    float* out = (float*)d_out;

    float *x, *xb, *zhat, *pcm;
    __half *Ah, *Bh, *Axo, *Bfo, *Axi, *Bfi, *W1p, *W2p;
    cudaGetSymbolAddress((void**)&x,    g_x);
    cudaGetSymbolAddress((void**)&xb,   g_xb);
    cudaGetSymbolAddress((void**)&zhat, g_zhat);
    cudaGetSymbolAddress((void**)&pcm,  g_pcm);
    cudaGetSymbolAddress((void**)&Ah,   g_Ah);
    cudaGetSymbolAddress((void**)&Bh,   g_Bh);
    cudaGetSymbolAddress((void**)&Axo,  g_Axo);
    cudaGetSymbolAddress((void**)&Bfo,  g_Bfo);
    cudaGetSymbolAddress((void**)&Axi,  g_Axi);
    cudaGetSymbolAddress((void**)&Bfi,  g_Bfi);
    cudaGetSymbolAddress((void**)&W1p,  g_W1p);
    cudaGetSymbolAddress((void**)&W2p,  g_W2p);

    cudaFuncSetAttribute(gemm_hmma, cudaFuncAttributeMaxDynamicSharedMemorySize,
                         HSMEM);
    cudaFuncSetAttribute(gemm_hmma_n256,
                         cudaFuncAttributeMaxDynamicSharedMemorySize, G256_SMEM);
    cudaFuncSetAttribute(mlp_tc, cudaFuncAttributeMaxDynamicSharedMemorySize,
                         MLPTC_SMEM);

    // 1. embed + weight conversions
    embed_kernel<<<S_TOT, 256>>>(ids, emb, pos, x);
    convB_h<<<V_DIM, 256>>>(emb, Bh);
    convB3T<<<dim3(D_DIM / 32, T_DIM / 32), 256>>>(fo_w, Bfo, D_DIM, T_DIM);
    convB3T<<<dim3(T_DIM / 32, D_DIM / 32), 256>>>(fi_w, Bfi, T_DIM, D_DIM);
    convW1p<<<512, 256>>>(W1, W1p);
    convW2p<<<512, 256>>>(W2, W2p);

    // 2. fan_out (HMMA 3-term)
    convA3<<<S_TOT, 256>>>(x, Axo, D_DIM);
    gemm_hmma<<<dim3(S_TOT / 128, T_DIM / 128), 256, HSMEM>>>(
        Axo, Bfo, fo_b, xb, 3 * D_DIM, 3 * D_DIM, T_DIM, 3 * D_DIM / 64, ~0);

    // 3. refine passes (fused z-pass + MLP on tensor cores)
    for (int r = 0; r < 3; r++) {
        mlp_tc<<<dim3(128, NB), 256, MLPTC_SMEM>>>(xb, W1p, W2p, Wz, zhat, pcm,
                                                   lamp, r);
    }

    // 4. fan_in (HMMA 3-term)
    convA3<<<S_TOT, 256>>>(xb, Axi, T_DIM);
    gemm_hmma<<<dim3(S_TOT / 128, D_DIM / 128), 256, HSMEM>>>(
        Axi, Bfi, fi_b, x, 3 * T_DIM, 3 * T_DIM, D_DIM, 3 * T_DIM / 64, ~0);

    // 5. layernorm
    ln_kernel<<<S_TOT, 256>>>(x, ln_g, ln_b);

    // 6. logits (HMMA 2-term A-split, 128x256 tile, B k-wrap)
    convA_h<<<S_TOT, 256>>>(x, Ah);
    gemm_hmma_n256<<<dim3(S_TOT / 128, V_DIM / 256), 256, G256_SMEM>>>(Ah, Bh,
                                                                       out);

    // 7. aux loss
    if (out_size > S_TOT * V_DIM) {
        aux_kernel<<<1, 256>>>(pcm, out + (size_t)S_TOT * V_DIM);
    }
}

// round 8
// speedup vs baseline: 1.0798x; 1.0798x over previous
#include <cuda_runtime.h>
#include <cuda_fp16.h>
#include <stdint.h>
#include <math.h>

// Problem dims
#define S_TOT 4096     // BS*N
#define D_DIM 1024
#define T_DIM 2048
#define V_DIM 32000
#define NB 8

// Scratch (device globals — allocation-free rule)
__device__ float g_x[S_TOT * D_DIM];
__device__ float g_xb[S_TOT * T_DIM];
__device__ float g_zhat[S_TOT * NB * 64];
__device__ float g_pcm[2 * S_TOT * NB];
__device__ __half g_Ah[(size_t)S_TOT * 2048];
__device__ __half g_Bh[(size_t)V_DIM * 1024];
__device__ __half g_Axo[(size_t)S_TOT * 3072];
__device__ __half g_Bfo[(size_t)T_DIM * 3072];
__device__ __half g_Axi[(size_t)S_TOT * 6144];
__device__ __half g_Bfi[(size_t)D_DIM * 6144];
__device__ __half g_W1p[NB * 256 * 64];
__device__ __half g_W2p[NB * 64 * 256];

__device__ __forceinline__ uint32_t smem_u32(const void* p) {
    uint32_t a;
    asm("{ .reg .u64 t; cvta.to.shared.u64 t, %1; cvt.u32.u64 %0, t; }"
        : "=r"(a) : "l"(p));
    return a;
}
__device__ __forceinline__ void ldsm4(uint32_t* r, uint32_t addr) {
    asm volatile("ldmatrix.sync.aligned.m8n8.x4.shared.b16 {%0,%1,%2,%3}, [%4];"
                 : "=r"(r[0]), "=r"(r[1]), "=r"(r[2]), "=r"(r[3]) : "r"(addr));
}
__device__ __forceinline__ void mma16816(float* c, const uint32_t* a,
                                         uint32_t b0, uint32_t b1) {
    asm volatile(
        "mma.sync.aligned.m16n8k16.row.col.f32.f16.f16.f32 "
        "{%0,%1,%2,%3}, {%4,%5,%6,%7}, {%8,%9}, {%0,%1,%2,%3};"
        : "+f"(c[0]), "+f"(c[1]), "+f"(c[2]), "+f"(c[3])
        : "r"(a[0]), "r"(a[1]), "r"(a[2]), "r"(a[3]), "r"(b0), "r"(b1));
}
__device__ __forceinline__ float gelu_f(float v) {
    float u = 0.7978845608028654f * (v + 0.044715f * v * v * v);
    float th;
    asm("tanh.approx.f32 %0, %1;" : "=f"(th) : "f"(u));
    return 0.5f * v * (1.0f + th);
}
__device__ __forceinline__ uint32_t pack_h2(float a, float b) {
    __half ha = __float2half_rn(a), hb = __float2half_rn(b);
    return (uint32_t)__half_as_ushort(ha) | ((uint32_t)__half_as_ushort(hb) << 16);
}

// ---------------------------------------------------------------------------
// Conversions
// ---------------------------------------------------------------------------
__global__ void convA_h(const float* __restrict__ x, __half* __restrict__ Ah) {
    int row = blockIdx.x;
    int q = threadIdx.x;
    float4 v = ((const float4*)(x + (size_t)row * 1024))[q];
    __half h0 = __float2half_rn(v.x), h1 = __float2half_rn(v.y);
    __half h2 = __float2half_rn(v.z), h3 = __float2half_rn(v.w);
    uint2 H, L;
    H.x = pack_h2(v.x, v.y); H.y = pack_h2(v.z, v.w);
    L.x = pack_h2(v.x - __half2float(h0), v.y - __half2float(h1));
    L.y = pack_h2(v.z - __half2float(h2), v.w - __half2float(h3));
    __half* base = Ah + (size_t)row * 2048 + q * 4;
    *(uint2*)base = H;
    *(uint2*)(base + 1024) = L;
}

__global__ void convB_h(const float* __restrict__ emb, __half* __restrict__ Bh) {
    size_t i = (size_t)blockIdx.x * 256 + threadIdx.x;
    float4 v = ((const float4*)emb)[i];
    uint2 H;
    H.x = pack_h2(v.x, v.y); H.y = pack_h2(v.z, v.w);
    ((uint2*)Bh)[i] = H;
}

__global__ void convA3(const float* __restrict__ src, __half* __restrict__ dst,
                       int K) {
    int row = blockIdx.x;
    const float4* sp = (const float4*)(src + (size_t)row * K);
    __half* base = dst + (size_t)row * 3 * K;
    for (int q = threadIdx.x; q < K / 4; q += 256) {
        float4 v = sp[q];
        __half h0 = __float2half_rn(v.x), h1 = __float2half_rn(v.y);
        __half h2 = __float2half_rn(v.z), h3 = __float2half_rn(v.w);
        uint2 H, L;
        H.x = pack_h2(v.x, v.y); H.y = pack_h2(v.z, v.w);
        L.x = pack_h2(v.x - __half2float(h0), v.y - __half2float(h1));
        L.y = pack_h2(v.z - __half2float(h2), v.w - __half2float(h3));
        *(uint2*)(base + q * 4)         = H;
        *(uint2*)(base + K + q * 4)     = L;
        *(uint2*)(base + 2 * K + q * 4) = H;
    }
}

__global__ void convB3T(const float* __restrict__ src, __half* __restrict__ dst,
                        int K, int N) {
    __shared__ float tile[32][33];
    int k0 = blockIdx.x * 32, n0 = blockIdx.y * 32;
    int tx = threadIdx.x & 31, ty = threadIdx.x >> 5;
    for (int i = ty; i < 32; i += 8)
        tile[i][tx] = src[(size_t)(k0 + i) * N + n0 + tx];
    __syncthreads();
    for (int i = ty; i < 32; i += 8) {
        int n = n0 + i;
        float v = tile[tx][i];
        __half h = __float2half_rn(v);
        __half l = __float2half_rn(v - __half2float(h));
        __half* row = dst + (size_t)n * 3 * K + k0 + tx;
        row[0]     = h;
        row[K]     = h;
        row[2 * K] = l;
    }
}

// Pre-swizzled fp16 weights for mlp_tc
__global__ void convW1p(const float* __restrict__ W1, __half* __restrict__ W1p) {
    int idx = blockIdx.x * 256 + threadIdx.x;
    int t = idx >> 14, rem = idx & 16383;
    int rr = rem >> 6, ph = (rem >> 3) & 7, j = rem & 7;
    int k = ((ph ^ (rr & 7)) << 3) | j;
    W1p[idx] = __float2half_rn(W1[((size_t)t * 64 + k) * 256 + rr]);
}
__global__ void convW2p(const float* __restrict__ W2, __half* __restrict__ W2p) {
    int idx = blockIdx.x * 256 + threadIdx.x;
    int t = idx >> 14, rem = idx & 16383;
    int rr = rem >> 8, ph = (rem >> 3) & 31, j = rem & 7;
    int c = (ph & ~7) | ((ph & 7) ^ (rr & 7));
    int k = (c << 3) | j;
    W2p[idx] = __float2half_rn(W2[((size_t)t * 256 + k) * 64 + rr]);
}

// ---------------------------------------------------------------------------
// HMMA fp16 GEMM, 128x128 tile (fan_out / fan_in / logits)
// ---------------------------------------------------------------------------
#define HBUF 32768
#define HSMEM (2 * HBUF)

__global__ __launch_bounds__(256) void gemm_hmma(
    const __half* __restrict__ A, const __half* __restrict__ B,
    const float* __restrict__ bias, float* __restrict__ C,
    int ldA, int ldB, int N, int nch, int bkmask) {
    extern __shared__ __align__(128) char smem[];
    const uint32_t sb = smem_u32(smem);
    const int tid = threadIdx.x, lane = tid & 31, wid = tid >> 5;
    const int bm = blockIdx.x * 128, bn = blockIdx.y * 128;
    const int wm = (wid & 1) * 64, wn = (wid >> 1) * 32;

    float acc[4][4][4] = {};

    auto issue = [&](int ch, int buf) {
        int k0 = ch * 64;
        int bk = k0 & bkmask;
        uint32_t abase = sb + buf * HBUF;
        uint32_t bbase = abase + 16384;
#pragma unroll
        for (int i = 0; i < 4; i++) {
            int idx = tid + 256 * i;
            int r = idx >> 3, c = idx & 7;
            uint32_t off = (uint32_t)(r * 128 + ((c ^ (r & 7)) * 16));
            const __half* gp = A + (size_t)(bm + r) * ldA + k0 + c * 8;
            asm volatile("cp.async.cg.shared.global [%0], [%1], 16;"
                         :: "r"(abase + off), "l"(gp));
        }
#pragma unroll
        for (int i = 0; i < 4; i++) {
            int idx = tid + 256 * i;
            int r = idx >> 3, c = idx & 7;
            uint32_t off = (uint32_t)(r * 128 + ((c ^ (r & 7)) * 16));
            const __half* gp = B + (size_t)(bn + r) * ldB + bk + c * 8;
            asm volatile("cp.async.cg.shared.global [%0], [%1], 16;"
                         :: "r"(bbase + off), "l"(gp));
        }
        asm volatile("cp.async.commit_group;" ::: "memory");
    };

    issue(0, 0);

    for (int ch = 0; ch < nch; ch++) {
        int b = ch & 1;
        if (ch + 1 < nch) {
            issue(ch + 1, b ^ 1);
            asm volatile("cp.async.wait_group 1;" ::: "memory");
        } else {
            asm volatile("cp.async.wait_group 0;" ::: "memory");
        }
        __syncthreads();

        uint32_t abase = sb + b * HBUF;
        uint32_t bbase = abase + 16384;
#pragma unroll
        for (int ks = 0; ks < 4; ks++) {
            uint32_t afr[4][4];
#pragma unroll
            for (int mi = 0; mi < 4; mi++) {
                int r = wm + mi * 16 + (lane & 15);
                int cu = ks * 2 + (lane >> 4);
                uint32_t addr = abase + r * 128 + ((cu ^ (r & 7)) * 16);
                ldsm4(afr[mi], addr);
            }
            uint32_t bfr[2][4];
#pragma unroll
            for (int p = 0; p < 2; p++) {
                int r = wn + p * 16 + (lane & 7) + ((lane >> 4) * 8);
                int cu = ks * 2 + ((lane >> 3) & 1);
                uint32_t addr = bbase + r * 128 + ((cu ^ (r & 7)) * 16);
                ldsm4(bfr[p], addr);
            }
#pragma unroll
            for (int mi = 0; mi < 4; mi++)
#pragma unroll
                for (int nj = 0; nj < 4; nj++)
                    mma16816(acc[mi][nj], afr[mi],
                             bfr[nj >> 1][(nj & 1) * 2 + 0],
                             bfr[nj >> 1][(nj & 1) * 2 + 1]);
        }
        __syncthreads();
    }

#pragma unroll
    for (int mi = 0; mi < 4; mi++) {
#pragma unroll
        for (int nj = 0; nj < 4; nj++) {
            int row = bm + wm + mi * 16 + (lane >> 2);
            int col = bn + wn + nj * 8 + (lane & 3) * 2;
            float b0 = bias ? bias[col] : 0.0f;
            float b1 = bias ? bias[col + 1] : 0.0f;
            float2 v0 = make_float2(acc[mi][nj][0] + b0, acc[mi][nj][1] + b1);
            float2 v1 = make_float2(acc[mi][nj][2] + b0, acc[mi][nj][3] + b1);
            *(float2*)(C + (size_t)row * N + col) = v0;
            *(float2*)(C + (size_t)(row + 8) * N + col) = v1;
        }
    }
}

// ---------------------------------------------------------------------------
// Fused HMMA refine MLP + z-pass (R7 version — kept; fusion bit-verified)
// ---------------------------------------------------------------------------
#define MLPTC_SMEM (163840 + 16384 + 8192)
__global__ __launch_bounds__(256) void mlp_tc(
    float* __restrict__ xb, const __half* __restrict__ W1p,
    const __half* __restrict__ W2p, const float* __restrict__ Wz,
    float* __restrict__ zhat, float* __restrict__ pcm,
    const float* __restrict__ lam_logit, int r) {
    extern __shared__ __align__(128) char smem[];
    const uint32_t sb = smem_u32(smem);
    const uint32_t XS = sb, W1S = sb + 32768, HS = sb, W2S = sb + 131072;
    const uint32_t WZS = sb + 163840;
    float* zsp = (float*)(smem + 180224);
    float* wzsp = (float*)(smem + 163840);
    const int tid = threadIdx.x, lane = tid & 31, wid = tid >> 5;
    const int t = blockIdx.y, rt = blockIdx.x;
    const int wm = (wid & 1) * 64;
    float lam = 1.0f;
    if (r > 0) lam = 1.0f / (1.0f + expf(-lam_logit[0]));

    // async-load weights: W1p, W2p (pre-swizzled fp16), Wz (fp32)
    {
        const __half* w1g = W1p + (size_t)t * 16384;
        const __half* w2g = W2p + (size_t)t * 16384;
        const float* wzg = Wz + (size_t)t * 4096;
#pragma unroll
        for (int i = 0; i < 8; i++) {
            int idx = tid + 256 * i;
            asm volatile("cp.async.cg.shared.global [%0], [%1], 16;"
                         :: "r"(W1S + idx * 16), "l"(w1g + idx * 8));
        }
#pragma unroll
        for (int i = 0; i < 8; i++) {
            int idx = tid + 256 * i;
            asm volatile("cp.async.cg.shared.global [%0], [%1], 16;"
                         :: "r"(W2S + idx * 16), "l"(w2g + idx * 8));
        }
#pragma unroll
        for (int i = 0; i < 4; i++) {
            int idx = tid + 256 * i;
            asm volatile("cp.async.cg.shared.global [%0], [%1], 16;"
                         :: "r"(WZS + idx * 16), "l"(wzg + idx * 4));
        }
        asm volatile("cp.async.commit_group;" ::: "memory");
    }

    // X tile: load fp32, split hi/lo fp16 into XS (row stride 256B, swizzled)
#pragma unroll
    for (int i = 0; i < 4; i++) {
        int idx = tid + 256 * i;
        int lr = idx >> 3, c = idx & 7;
        int g = rt * 128 + lr;
        const float* xp = xb + ((size_t)(g >> 2) * 32 + t * 4 + (g & 3)) * 64 + c * 8;
        float4 v0 = *(const float4*)xp;
        float4 v1 = *(const float4*)(xp + 4);
        float vv[8] = {v0.x, v0.y, v0.z, v0.w, v1.x, v1.y, v1.z, v1.w};
        uint4 Hh, Ll;
        uint32_t* hw = (uint32_t*)&Hh;
        uint32_t* lw = (uint32_t*)&Ll;
#pragma unroll
        for (int j = 0; j < 4; j++) {
            float a = vv[2 * j], b = vv[2 * j + 1];
            __half ha = __float2half_rn(a), hb = __float2half_rn(b);
            hw[j] = (uint32_t)__half_as_ushort(ha) |
                    ((uint32_t)__half_as_ushort(hb) << 16);
            lw[j] = pack_h2(a - __half2float(ha), b - __half2float(hb));
        }
        int phh = c ^ (lr & 7);
        *(uint4*)(smem + lr * 256 + phh * 16) = Hh;
        *(uint4*)(smem + lr * 256 + (8 + phh) * 16) = Ll;
    }
    __syncthreads();  // XS visible

    // z = mean_c (hi+lo reconstruction ~fp32-exact)
    {
        int s_loc = tid >> 3;
        int d0 = (tid & 7) * 8;
        float zv[8] = {};
#pragma unroll
        for (int c = 0; c < 4; c++) {
            int lr = s_loc * 4 + c;
            int byte_off = lr * 256 + (((d0 >> 3) ^ (lr & 7)) * 16);
            uint4 hi = *(const uint4*)(smem + byte_off);
            uint4 lo = *(const uint4*)(smem + byte_off + 128);
            const __half2* hp = (const __half2*)&hi;
            const __half2* lp = (const __half2*)&lo;
#pragma unroll
            for (int j = 0; j < 4; j++) {
                float2 h2 = __half22float2(hp[j]);
                float2 l2 = __half22float2(lp[j]);
                zv[2 * j]     += h2.x + l2.x;
                zv[2 * j + 1] += h2.y + l2.y;
            }
        }
#pragma unroll
        for (int j = 0; j < 8; j++) zsp[s_loc * 64 + d0 + j] = 0.25f * zv[j];
    }
    asm volatile("cp.async.wait_group 0;" ::: "memory");  // weights in
    __syncthreads();  // ZS + weights visible

    // pcm (r>0) + zhat = z @ Wz[t]
    {
        int s_loc = tid >> 3, e0 = (tid & 7) * 8;
        int st = (rt * 32 + s_loc) * 8 + t;
        const float* zr = zsp + s_loc * 64;
        float acc[8] = {};
        for (int d = 0; d < 64; d++) {
            float zv = zr[d];
            const float* wr = wzsp + d * 64 + e0;
#pragma unroll
            for (int j = 0; j < 8; j++) acc[j] = fmaf(zv, wr[j], acc[j]);
        }
        if (r > 0) {
            float sq = 0.0f;
#pragma unroll
            for (int j = 0; j < 8; j++) {
                float diff = zhat[(size_t)st * 64 + e0 + j] - zr[e0 + j];
                sq = fmaf(diff, diff, sq);
            }
            sq += __shfl_down_sync(0xffffffffu, sq, 4, 8);
            sq += __shfl_down_sync(0xffffffffu, sq, 2, 8);
            sq += __shfl_down_sync(0xffffffffu, sq, 1, 8);
            if ((tid & 7) == 0)
                pcm[(size_t)(r - 1) * (S_TOT * NB) + st] = sq;
        }
#pragma unroll
        for (int j = 0; j < 8; j++) zhat[(size_t)st * 64 + e0 + j] = acc[j];
    }

    // Phase 1: H[128x256] = gelu(X2 @ W1h), warp tile 64x64
    float acc1[4][8][4] = {};
    {
        const int wn1 = (wid >> 1) * 64;
#pragma unroll
        for (int ks = 0; ks < 8; ks++) {
            uint32_t afr[4][4];
#pragma unroll
            for (int mi = 0; mi < 4; mi++) {
                int rr = wm + mi * 16 + (lane & 15);
                int cu = ks * 2 + (lane >> 4);
                int ph = (cu & 8) | ((cu & 7) ^ (rr & 7));
                ldsm4(afr[mi], XS + rr * 256 + ph * 16);
            }
            uint32_t bfr[4][4];
#pragma unroll
            for (int p = 0; p < 4; p++) {
                int rr = wn1 + p * 16 + (lane & 7) + ((lane >> 4) * 8);
                int cu = (ks * 2 + ((lane >> 3) & 1)) & 7;
                int ph = cu ^ (rr & 7);
                ldsm4(bfr[p], W1S + rr * 128 + ph * 16);
            }
#pragma unroll
            for (int mi = 0; mi < 4; mi++)
#pragma unroll
                for (int nj = 0; nj < 8; nj++)
                    mma16816(acc1[mi][nj], afr[mi],
                             bfr[nj >> 1][(nj & 1) * 2 + 0],
                             bfr[nj >> 1][(nj & 1) * 2 + 1]);
        }
        __syncthreads();  // phase1 smem reads done (XS/W1S free)

        const int wn1b = (wid >> 1) * 64;
#pragma unroll
        for (int mi = 0; mi < 4; mi++)
#pragma unroll
            for (int nj = 0; nj < 8; nj++) {
                int r0 = wm + mi * 16 + (lane >> 2);
                int n0 = wn1b + nj * 8 + (lane & 3) * 2;
                float g0 = gelu_f(acc1[mi][nj][0]);
                float g1 = gelu_f(acc1[mi][nj][1]);
                float g2 = gelu_f(acc1[mi][nj][2]);
                float g3 = gelu_f(acc1[mi][nj][3]);
                __half h0 = __float2half_rn(g0), h1 = __float2half_rn(g1);
                __half h2 = __float2half_rn(g2), h3 = __float2half_rn(g3);
                uint32_t hi0 = (uint32_t)__half_as_ushort(h0) |
                               ((uint32_t)__half_as_ushort(h1) << 16);
                uint32_t hi1 = (uint32_t)__half_as_ushort(h2) |
                               ((uint32_t)__half_as_ushort(h3) << 16);
                uint32_t lo0 = pack_h2(g0 - __half2float(h0), g1 - __half2float(h1));
                uint32_t lo1 = pack_h2(g2 - __half2float(h2), g3 - __half2float(h3));
                int ch = n0 >> 3, within = (n0 & 7) * 2;
                int ph = (ch & ~7) | ((ch & 7) ^ (r0 & 7));
                char* base0 = smem + r0 * 1024 + within;
                char* base1 = smem + (r0 + 8) * 1024 + within;
                *(uint32_t*)(base0 + ph * 16) = hi0;
                *(uint32_t*)(base0 + (ph + 32) * 16) = lo0;
                *(uint32_t*)(base1 + ph * 16) = hi1;
                *(uint32_t*)(base1 + (ph + 32) * 16) = lo1;
            }
    }
    __syncthreads();

    // Phase 2: delta[128x64], warp tile 64x16, K'=512
    float acc2[4][2][4] = {};
    const int wn2 = (wid >> 1) * 16;
#pragma unroll
    for (int ks = 0; ks < 32; ks++) {
        uint32_t afr[4][4];
#pragma unroll
        for (int mi = 0; mi < 4; mi++) {
            int rr = wm + mi * 16 + (lane & 15);
            int cu = ks * 2 + (lane >> 4);
            int ph = (cu & ~7) | ((cu & 7) ^ (rr & 7));
            ldsm4(afr[mi], HS + rr * 1024 + ph * 16);
        }
        uint32_t bfr[4];
        {
            int rr = wn2 + (lane & 7) + ((lane >> 4) * 8);
            int cu = (ks * 2 + ((lane >> 3) & 1)) & 31;
            int ph = (cu & ~7) | ((cu & 7) ^ (rr & 7));
            ldsm4(bfr, W2S + rr * 512 + ph * 16);
        }
#pragma unroll
        for (int mi = 0; mi < 4; mi++)
#pragma unroll
            for (int nj = 0; nj < 2; nj++)
                mma16816(acc2[mi][nj], afr[mi], bfr[nj * 2], bfr[nj * 2 + 1]);
    }

    // Epilogue: xb += lam * delta
#pragma unroll
    for (int mi = 0; mi < 4; mi++)
#pragma unroll
        for (int nj = 0; nj < 2; nj++) {
            int r0 = wm + mi * 16 + (lane >> 2);
            int n0 = wn2 + nj * 8 + (lane & 3) * 2;
#pragma unroll
            for (int h = 0; h < 2; h++) {
                int g = rt * 128 + r0 + h * 8;
                float* p = xb + ((size_t)(g >> 2) * 32 + t * 4 + (g & 3)) * 64 + n0;
                float2 old = *(float2*)p;
                old.x += lam * acc2[mi][nj][h * 2 + 0];
                old.y += lam * acc2[mi][nj][h * 2 + 1];
                *(float2*)p = old;
            }
        }
}

// ---------------------------------------------------------------------------
// Embedding gather + pos add
// ---------------------------------------------------------------------------
__global__ void embed_kernel(const int* __restrict__ ids,
                             const float* __restrict__ emb,
                             const float* __restrict__ pos,
                             float* __restrict__ x) {
    int s = blockIdx.x;
    int q = threadIdx.x;
    int id = ids[s];
    float4 e = ((const float4*)(emb + (size_t)id * D_DIM))[q];
    float4 p = ((const float4*)(pos + (size_t)(s & 1023) * D_DIM))[q];
    float4 o;
    o.x = e.x + p.x; o.y = e.y + p.y; o.z = e.z + p.z; o.w = e.w + p.w;
    ((float4*)(x + (size_t)s * D_DIM))[q] = o;
}

// ---------------------------------------------------------------------------
// LayerNorm (in place)
// ---------------------------------------------------------------------------
__global__ void ln_kernel(float* __restrict__ x, const float* __restrict__ g,
                          const float* __restrict__ b) {
    __shared__ float red[256];
    const int s = blockIdx.x, tid = threadIdx.x;
    float4* row = (float4*)(x + (size_t)s * D_DIM);
    float4 v = row[tid];
    red[tid] = v.x + v.y + v.z + v.w;
    __syncthreads();
    for (int o = 128; o > 0; o >>= 1) {
        if (tid < o) red[tid] += red[tid + o];
        __syncthreads();
    }
    float mu = red[0] * (1.0f / 1024.0f);
    __syncthreads();
    float dx = v.x - mu, dy = v.y - mu, dz = v.z - mu, dw = v.w - mu;
    red[tid] = dx * dx + dy * dy + dz * dz + dw * dw;
    __syncthreads();
    for (int o = 128; o > 0; o >>= 1) {
        if (tid < o) red[tid] += red[tid + o];
        __syncthreads();
    }
    float rstd = rsqrtf(red[0] * (1.0f / 1024.0f) + 1e-5f);
    float4 gg = ((const float4*)g)[tid];
    float4 bb = ((const float4*)b)[tid];
    float4 o4;
    o4.x = dx * rstd * gg.x + bb.x;
    o4.y = dy * rstd * gg.y + bb.y;
    o4.z = dz * rstd * gg.z + bb.z;
    o4.w = dw * rstd * gg.w + bb.w;
    row[tid] = o4;
}

// ---------------------------------------------------------------------------
// Deterministic aux reduction
// ---------------------------------------------------------------------------
__global__ void aux_kernel(const float* __restrict__ pcm, float* __restrict__ out) {
    __shared__ float red[256];
    const int tid = threadIdx.x;
    float s = 0.0f;
    for (int i = tid; i < 2 * S_TOT * NB; i += 256) s += pcm[i];
    red[tid] = s;
    __syncthreads();
    for (int o = 128; o > 0; o >>= 1) {
        if (tid < o) red[tid] += red[tid + o];
        __syncthreads();
    }
    if (tid == 0) out[0] = 0.1f * red[0] / 262144.0f;
}

// ---------------------------------------------------------------------------
extern "C" void kernel_launch(void* const* d_in, const int* in_sizes, int n_in,
                              void* d_out, int out_size) {
    const int*   ids  = (const int*)d_in[0];
    const float* emb  = (const float*)d_in[1];
    const float* pos  = (const float*)d_in[2];
    const float* fo_w = (const float*)d_in[3];
    const float* fo_b = (const float*)d_in[4];
    const float* W1   = (const float*)d_in[5];
    const float* W2   = (const float*)d_in[6];
    const float* Wz   = (const float*)d_in[7];
    const float* fi_w = (const float*)d_in[8];
    const float* fi_b = (const float*)d_in[9];
    const float* ln_g = (const float*)d_in[10];
    const float* ln_b = (const float*)d_in[11];
    const float* lamp = (const float*)d_in[12];
    float* out = (float*)d_out;

    float *x, *xb, *zhat, *pcm;
    __half *Ah, *Bh, *Axo, *Bfo, *Axi, *Bfi, *W1p, *W2p;
    cudaGetSymbolAddress((void**)&x,    g_x);
    cudaGetSymbolAddress((void**)&xb,   g_xb);
    cudaGetSymbolAddress((void**)&zhat, g_zhat);
    cudaGetSymbolAddress((void**)&pcm,  g_pcm);
    cudaGetSymbolAddress((void**)&Ah,   g_Ah);
    cudaGetSymbolAddress((void**)&Bh,   g_Bh);
    cudaGetSymbolAddress((void**)&Axo,  g_Axo);
    cudaGetSymbolAddress((void**)&Bfo,  g_Bfo);
    cudaGetSymbolAddress((void**)&Axi,  g_Axi);
    cudaGetSymbolAddress((void**)&Bfi,  g_Bfi);
    cudaGetSymbolAddress((void**)&W1p,  g_W1p);
    cudaGetSymbolAddress((void**)&W2p,  g_W2p);

    cudaFuncSetAttribute(gemm_hmma, cudaFuncAttributeMaxDynamicSharedMemorySize,
                         HSMEM);
    cudaFuncSetAttribute(mlp_tc, cudaFuncAttributeMaxDynamicSharedMemorySize,
                         MLPTC_SMEM);

    // 1. embed + weight conversions
    embed_kernel<<<S_TOT, 256>>>(ids, emb, pos, x);
    convB_h<<<V_DIM, 256>>>(emb, Bh);
    convB3T<<<dim3(D_DIM / 32, T_DIM / 32), 256>>>(fo_w, Bfo, D_DIM, T_DIM);
    convB3T<<<dim3(T_DIM / 32, D_DIM / 32), 256>>>(fi_w, Bfi, T_DIM, D_DIM);
    convW1p<<<512, 256>>>(W1, W1p);
    convW2p<<<512, 256>>>(W2, W2p);

    // 2. fan_out (HMMA 3-term)
    convA3<<<S_TOT, 256>>>(x, Axo, D_DIM);
    gemm_hmma<<<dim3(S_TOT / 128, T_DIM / 128), 256, HSMEM>>>(
        Axo, Bfo, fo_b, xb, 3 * D_DIM, 3 * D_DIM, T_DIM, 3 * D_DIM / 64, ~0);

    // 3. refine passes (fused z-pass + MLP on tensor cores)
    for (int r = 0; r < 3; r++) {
        mlp_tc<<<dim3(128, NB), 256, MLPTC_SMEM>>>(xb, W1p, W2p, Wz, zhat, pcm,
                                                   lamp, r);
    }

    // 4. fan_in (HMMA 3-term)
    convA3<<<S_TOT, 256>>>(xb, Axi, T_DIM);
    gemm_hmma<<<dim3(S_TOT / 128, D_DIM / 128), 256, HSMEM>>>(
        Axi, Bfi, fi_b, x, 3 * T_DIM, 3 * T_DIM, D_DIM, 3 * T_DIM / 64, ~0);

    // 5. layernorm
    ln_kernel<<<S_TOT, 256>>>(x, ln_g, ln_b);

    // 6. logits (HMMA 2-term A-split, 128x128 tile — proven config)
    convA_h<<<S_TOT, 256>>>(x, Ah);
    gemm_hmma<<<dim3(S_TOT / 128, V_DIM / 128), 256, HSMEM>>>(
        Ah, Bh, (const float*)0, out, 2048, 1024, V_DIM, 32, 1023);

    // 7. aux loss
    if (out_size > S_TOT * V_DIM) {
        aux_kernel<<<1, 256>>>(pcm, out + (size_t)S_TOT * V_DIM);
    }
}

// round 9
// speedup vs baseline: 1.5071x; 1.3957x over previous
#include <cuda_runtime.h>
#include <cuda_fp16.h>
#include <stdint.h>
#include <math.h>

// Problem dims
#define S_TOT 4096     // BS*N
#define D_DIM 1024
#define T_DIM 2048
#define V_DIM 32000
#define NB 8

// Scratch (device globals — allocation-free rule)
__device__ float g_x[S_TOT * D_DIM];
__device__ float g_xb[S_TOT * T_DIM];
__device__ float g_zhat[S_TOT * NB * 64];
__device__ float g_pcm[2 * S_TOT * NB];
__device__ __half g_Ah[(size_t)S_TOT * 1024];    // logits A plain fp16
__device__ __half g_Bh[(size_t)V_DIM * 1024];
__device__ __half g_Axo[(size_t)S_TOT * 3072];
__device__ __half g_Bfo[(size_t)T_DIM * 3072];
__device__ __half g_Axi[(size_t)S_TOT * 6144];
__device__ __half g_Bfi[(size_t)D_DIM * 6144];
__device__ __half g_W1p[NB * 256 * 64];
__device__ __half g_W2p[NB * 64 * 256];

__device__ __forceinline__ uint32_t smem_u32(const void* p) {
    uint32_t a;
    asm("{ .reg .u64 t; cvta.to.shared.u64 t, %1; cvt.u32.u64 %0, t; }"
        : "=r"(a) : "l"(p));
    return a;
}
__device__ __forceinline__ void ldsm4(uint32_t* r, uint32_t addr) {
    asm volatile("ldmatrix.sync.aligned.m8n8.x4.shared.b16 {%0,%1,%2,%3}, [%4];"
                 : "=r"(r[0]), "=r"(r[1]), "=r"(r[2]), "=r"(r[3]) : "r"(addr));
}
__device__ __forceinline__ void mma16816(float* c, const uint32_t* a,
                                         uint32_t b0, uint32_t b1) {
    asm volatile(
        "mma.sync.aligned.m16n8k16.row.col.f32.f16.f16.f32 "
        "{%0,%1,%2,%3}, {%4,%5,%6,%7}, {%8,%9}, {%0,%1,%2,%3};"
        : "+f"(c[0]), "+f"(c[1]), "+f"(c[2]), "+f"(c[3])
        : "r"(a[0]), "r"(a[1]), "r"(a[2]), "r"(a[3]), "r"(b0), "r"(b1));
}
__device__ __forceinline__ float gelu_f(float v) {
    float u = 0.7978845608028654f * (v + 0.044715f * v * v * v);
    float th;
    asm("tanh.approx.f32 %0, %1;" : "=f"(th) : "f"(u));
    return 0.5f * v * (1.0f + th);
}
__device__ __forceinline__ uint32_t pack_h2(float a, float b) {
    __half ha = __float2half_rn(a), hb = __float2half_rn(b);
    return (uint32_t)__half_as_ushort(ha) | ((uint32_t)__half_as_ushort(hb) << 16);
}

// ---------------------------------------------------------------------------
// Conversions
// ---------------------------------------------------------------------------
// A plain fp16 (logits path): x [4096,1024] f32 -> Ah [4096,1024] fp16
__global__ void convA_h(const float* __restrict__ x, __half* __restrict__ Ah) {
    size_t i = (size_t)blockIdx.x * 256 + threadIdx.x;
    float4 v = ((const float4*)x)[i];
    uint2 H;
    H.x = pack_h2(v.x, v.y); H.y = pack_h2(v.z, v.w);
    ((uint2*)Ah)[i] = H;
}

__global__ void convB_h(const float* __restrict__ emb, __half* __restrict__ Bh) {
    size_t i = (size_t)blockIdx.x * 256 + threadIdx.x;
    float4 v = ((const float4*)emb)[i];
    uint2 H;
    H.x = pack_h2(v.x, v.y); H.y = pack_h2(v.z, v.w);
    ((uint2*)Bh)[i] = H;
}

__global__ void convA3(const float* __restrict__ src, __half* __restrict__ dst,
                       int K) {
    int row = blockIdx.x;
    const float4* sp = (const float4*)(src + (size_t)row * K);
    __half* base = dst + (size_t)row * 3 * K;
    for (int q = threadIdx.x; q < K / 4; q += 256) {
        float4 v = sp[q];
        __half h0 = __float2half_rn(v.x), h1 = __float2half_rn(v.y);
        __half h2 = __float2half_rn(v.z), h3 = __float2half_rn(v.w);
        uint2 H, L;
        H.x = pack_h2(v.x, v.y); H.y = pack_h2(v.z, v.w);
        L.x = pack_h2(v.x - __half2float(h0), v.y - __half2float(h1));
        L.y = pack_h2(v.z - __half2float(h2), v.w - __half2float(h3));
        *(uint2*)(base + q * 4)         = H;
        *(uint2*)(base + K + q * 4)     = L;
        *(uint2*)(base + 2 * K + q * 4) = H;
    }
}

__global__ void convB3T(const float* __restrict__ src, __half* __restrict__ dst,
                        int K, int N) {
    __shared__ float tile[32][33];
    int k0 = blockIdx.x * 32, n0 = blockIdx.y * 32;
    int tx = threadIdx.x & 31, ty = threadIdx.x >> 5;
    for (int i = ty; i < 32; i += 8)
        tile[i][tx] = src[(size_t)(k0 + i) * N + n0 + tx];
    __syncthreads();
    for (int i = ty; i < 32; i += 8) {
        int n = n0 + i;
        float v = tile[tx][i];
        __half h = __float2half_rn(v);
        __half l = __float2half_rn(v - __half2float(h));
        __half* row = dst + (size_t)n * 3 * K + k0 + tx;
        row[0]     = h;
        row[K]     = h;
        row[2 * K] = l;
    }
}

// Pre-swizzled fp16 weights for mlp_tc
__global__ void convW1p(const float* __restrict__ W1, __half* __restrict__ W1p) {
    int idx = blockIdx.x * 256 + threadIdx.x;
    int t = idx >> 14, rem = idx & 16383;
    int rr = rem >> 6, ph = (rem >> 3) & 7, j = rem & 7;
    int k = ((ph ^ (rr & 7)) << 3) | j;
    W1p[idx] = __float2half_rn(W1[((size_t)t * 64 + k) * 256 + rr]);
}
__global__ void convW2p(const float* __restrict__ W2, __half* __restrict__ W2p) {
    int idx = blockIdx.x * 256 + threadIdx.x;
    int t = idx >> 14, rem = idx & 16383;
    int rr = rem >> 8, ph = (rem >> 3) & 31, j = rem & 7;
    int c = (ph & ~7) | ((ph & 7) ^ (rr & 7));
    int k = (c << 3) | j;
    W2p[idx] = __float2half_rn(W2[((size_t)t * 256 + k) * 64 + rr]);
}

// ---------------------------------------------------------------------------
// HMMA fp16 GEMM, 128x128 tile (fan_out / fan_in / logits)
// ---------------------------------------------------------------------------
#define HBUF 32768
#define HSMEM (2 * HBUF)

__global__ __launch_bounds__(256) void gemm_hmma(
    const __half* __restrict__ A, const __half* __restrict__ B,
    const float* __restrict__ bias, float* __restrict__ C,
    int ldA, int ldB, int N, int nch, int bkmask) {
    extern __shared__ __align__(128) char smem[];
    const uint32_t sb = smem_u32(smem);
    const int tid = threadIdx.x, lane = tid & 31, wid = tid >> 5;
    const int bm = blockIdx.x * 128, bn = blockIdx.y * 128;
    const int wm = (wid & 1) * 64, wn = (wid >> 1) * 32;

    float acc[4][4][4] = {};

    auto issue = [&](int ch, int buf) {
        int k0 = ch * 64;
        int bk = k0 & bkmask;
        uint32_t abase = sb + buf * HBUF;
        uint32_t bbase = abase + 16384;
#pragma unroll
        for (int i = 0; i < 4; i++) {
            int idx = tid + 256 * i;
            int r = idx >> 3, c = idx & 7;
            uint32_t off = (uint32_t)(r * 128 + ((c ^ (r & 7)) * 16));
            const __half* gp = A + (size_t)(bm + r) * ldA + k0 + c * 8;
            asm volatile("cp.async.cg.shared.global [%0], [%1], 16;"
                         :: "r"(abase + off), "l"(gp));
        }
#pragma unroll
        for (int i = 0; i < 4; i++) {
            int idx = tid + 256 * i;
            int r = idx >> 3, c = idx & 7;
            uint32_t off = (uint32_t)(r * 128 + ((c ^ (r & 7)) * 16));
            const __half* gp = B + (size_t)(bn + r) * ldB + bk + c * 8;
            asm volatile("cp.async.cg.shared.global [%0], [%1], 16;"
                         :: "r"(bbase + off), "l"(gp));
        }
        asm volatile("cp.async.commit_group;" ::: "memory");
    };

    issue(0, 0);

    for (int ch = 0; ch < nch; ch++) {
        int b = ch & 1;
        if (ch + 1 < nch) {
            issue(ch + 1, b ^ 1);
            asm volatile("cp.async.wait_group 1;" ::: "memory");
        } else {
            asm volatile("cp.async.wait_group 0;" ::: "memory");
        }
        __syncthreads();

        uint32_t abase = sb + b * HBUF;
        uint32_t bbase = abase + 16384;
#pragma unroll
        for (int ks = 0; ks < 4; ks++) {
            uint32_t afr[4][4];
#pragma unroll
            for (int mi = 0; mi < 4; mi++) {
                int r = wm + mi * 16 + (lane & 15);
                int cu = ks * 2 + (lane >> 4);
                uint32_t addr = abase + r * 128 + ((cu ^ (r & 7)) * 16);
                ldsm4(afr[mi], addr);
            }
            uint32_t bfr[2][4];
#pragma unroll
            for (int p = 0; p < 2; p++) {
                int r = wn + p * 16 + (lane & 7) + ((lane >> 4) * 8);
                int cu = ks * 2 + ((lane >> 3) & 1);
                uint32_t addr = bbase + r * 128 + ((cu ^ (r & 7)) * 16);
                ldsm4(bfr[p], addr);
            }
#pragma unroll
            for (int mi = 0; mi < 4; mi++)
#pragma unroll
                for (int nj = 0; nj < 4; nj++)
                    mma16816(acc[mi][nj], afr[mi],
                             bfr[nj >> 1][(nj & 1) * 2 + 0],
                             bfr[nj >> 1][(nj & 1) * 2 + 1]);
        }
        __syncthreads();
    }

#pragma unroll
    for (int mi = 0; mi < 4; mi++) {
#pragma unroll
        for (int nj = 0; nj < 4; nj++) {
            int row = bm + wm + mi * 16 + (lane >> 2);
            int col = bn + wn + nj * 8 + (lane & 3) * 2;
            float b0 = bias ? bias[col] : 0.0f;
            float b1 = bias ? bias[col + 1] : 0.0f;
            float2 v0 = make_float2(acc[mi][nj][0] + b0, acc[mi][nj][1] + b1);
            float2 v1 = make_float2(acc[mi][nj][2] + b0, acc[mi][nj][3] + b1);
            *(float2*)(C + (size_t)row * N + col) = v0;
            *(float2*)(C + (size_t)(row + 8) * N + col) = v1;
        }
    }
}

// ---------------------------------------------------------------------------
// Fused HMMA refine MLP + z-pass
// ---------------------------------------------------------------------------
#define MLPTC_SMEM (163840 + 16384 + 8192)
__global__ __launch_bounds__(256) void mlp_tc(
    float* __restrict__ xb, const __half* __restrict__ W1p,
    const __half* __restrict__ W2p, const float* __restrict__ Wz,
    float* __restrict__ zhat, float* __restrict__ pcm,
    const float* __restrict__ lam_logit, int r) {
    extern __shared__ __align__(128) char smem[];
    const uint32_t sb = smem_u32(smem);
    const uint32_t XS = sb, W1S = sb + 32768, HS = sb, W2S = sb + 131072;
    const uint32_t WZS = sb + 163840;
    float* zsp = (float*)(smem + 180224);
    float* wzsp = (float*)(smem + 163840);
    const int tid = threadIdx.x, lane = tid & 31, wid = tid >> 5;
    const int t = blockIdx.y, rt = blockIdx.x;
    const int wm = (wid & 1) * 64;
    float lam = 1.0f;
    if (r > 0) lam = 1.0f / (1.0f + expf(-lam_logit[0]));

    // async-load weights: W1p, W2p (pre-swizzled fp16), Wz (fp32)
    {
        const __half* w1g = W1p + (size_t)t * 16384;
        const __half* w2g = W2p + (size_t)t * 16384;
        const float* wzg = Wz + (size_t)t * 4096;
#pragma unroll
        for (int i = 0; i < 8; i++) {
            int idx = tid + 256 * i;
            asm volatile("cp.async.cg.shared.global [%0], [%1], 16;"
                         :: "r"(W1S + idx * 16), "l"(w1g + idx * 8));
        }
#pragma unroll
        for (int i = 0; i < 8; i++) {
            int idx = tid + 256 * i;
            asm volatile("cp.async.cg.shared.global [%0], [%1], 16;"
                         :: "r"(W2S + idx * 16), "l"(w2g + idx * 8));
        }
#pragma unroll
        for (int i = 0; i < 4; i++) {
            int idx = tid + 256 * i;
            asm volatile("cp.async.cg.shared.global [%0], [%1], 16;"
                         :: "r"(WZS + idx * 16), "l"(wzg + idx * 4));
        }
        asm volatile("cp.async.commit_group;" ::: "memory");
    }

    // X tile: load fp32, split hi/lo fp16 into XS (row stride 256B, swizzled)
#pragma unroll
    for (int i = 0; i < 4; i++) {
        int idx = tid + 256 * i;
        int lr = idx >> 3, c = idx & 7;
        int g = rt * 128 + lr;
        const float* xp = xb + ((size_t)(g >> 2) * 32 + t * 4 + (g & 3)) * 64 + c * 8;
        float4 v0 = *(const float4*)xp;
        float4 v1 = *(const float4*)(xp + 4);
        float vv[8] = {v0.x, v0.y, v0.z, v0.w, v1.x, v1.y, v1.z, v1.w};
        uint4 Hh, Ll;
        uint32_t* hw = (uint32_t*)&Hh;
        uint32_t* lw = (uint32_t*)&Ll;
#pragma unroll
        for (int j = 0; j < 4; j++) {
            float a = vv[2 * j], b = vv[2 * j + 1];
            __half ha = __float2half_rn(a), hb = __float2half_rn(b);
            hw[j] = (uint32_t)__half_as_ushort(ha) |
                    ((uint32_t)__half_as_ushort(hb) << 16);
            lw[j] = pack_h2(a - __half2float(ha), b - __half2float(hb));
        }
        int phh = c ^ (lr & 7);
        *(uint4*)(smem + lr * 256 + phh * 16) = Hh;
        *(uint4*)(smem + lr * 256 + (8 + phh) * 16) = Ll;
    }
    __syncthreads();  // XS visible

    // z = mean_c (hi+lo reconstruction ~fp32-exact)
    {
        int s_loc = tid >> 3;
        int d0 = (tid & 7) * 8;
        float zv[8] = {};
#pragma unroll
        for (int c = 0; c < 4; c++) {
            int lr = s_loc * 4 + c;
            int byte_off = lr * 256 + (((d0 >> 3) ^ (lr & 7)) * 16);
            uint4 hi = *(const uint4*)(smem + byte_off);
            uint4 lo = *(const uint4*)(smem + byte_off + 128);
            const __half2* hp = (const __half2*)&hi;
            const __half2* lp = (const __half2*)&lo;
#pragma unroll
            for (int j = 0; j < 4; j++) {
                float2 h2 = __half22float2(hp[j]);
                float2 l2 = __half22float2(lp[j]);
                zv[2 * j]     += h2.x + l2.x;
                zv[2 * j + 1] += h2.y + l2.y;
            }
        }
#pragma unroll
        for (int j = 0; j < 8; j++) zsp[s_loc * 64 + d0 + j] = 0.25f * zv[j];
    }
    asm volatile("cp.async.wait_group 0;" ::: "memory");  // weights in
    __syncthreads();  // ZS + weights visible

    // pcm (r>0) + zhat = z @ Wz[t]
    {
        int s_loc = tid >> 3, e0 = (tid & 7) * 8;
        int st = (rt * 32 + s_loc) * 8 + t;
        const float* zr = zsp + s_loc * 64;
        float acc[8] = {};
        for (int d = 0; d < 64; d++) {
            float zv = zr[d];
            const float* wr = wzsp + d * 64 + e0;
#pragma unroll
            for (int j = 0; j < 8; j++) acc[j] = fmaf(zv, wr[j], acc[j]);
        }
        if (r > 0) {
            float sq = 0.0f;
#pragma unroll
            for (int j = 0; j < 8; j++) {
                float diff = zhat[(size_t)st * 64 + e0 + j] - zr[e0 + j];
                sq = fmaf(diff, diff, sq);
            }
            sq += __shfl_down_sync(0xffffffffu, sq, 4, 8);
            sq += __shfl_down_sync(0xffffffffu, sq, 2, 8);
            sq += __shfl_down_sync(0xffffffffu, sq, 1, 8);
            if ((tid & 7) == 0)
                pcm[(size_t)(r - 1) * (S_TOT * NB) + st] = sq;
        }
#pragma unroll
        for (int j = 0; j < 8; j++) zhat[(size_t)st * 64 + e0 + j] = acc[j];
    }

    // Phase 1: H[128x256] = gelu(X2 @ W1h), warp tile 64x64
    float acc1[4][8][4] = {};
    {
        const int wn1 = (wid >> 1) * 64;
#pragma unroll
        for (int ks = 0; ks < 8; ks++) {
            uint32_t afr[4][4];
#pragma unroll
            for (int mi = 0; mi < 4; mi++) {
                int rr = wm + mi * 16 + (lane & 15);
                int cu = ks * 2 + (lane >> 4);
                int ph = (cu & 8) | ((cu & 7) ^ (rr & 7));
                ldsm4(afr[mi], XS + rr * 256 + ph * 16);
            }
            uint32_t bfr[4][4];
#pragma unroll
            for (int p = 0; p < 4; p++) {
                int rr = wn1 + p * 16 + (lane & 7) + ((lane >> 4) * 8);
                int cu = (ks * 2 + ((lane >> 3) & 1)) & 7;
                int ph = cu ^ (rr & 7);
                ldsm4(bfr[p], W1S + rr * 128 + ph * 16);
            }
#pragma unroll
            for (int mi = 0; mi < 4; mi++)
#pragma unroll
                for (int nj = 0; nj < 8; nj++)
                    mma16816(acc1[mi][nj], afr[mi],
                             bfr[nj >> 1][(nj & 1) * 2 + 0],
                             bfr[nj >> 1][(nj & 1) * 2 + 1]);
        }
        __syncthreads();  // phase1 smem reads done (XS/W1S free)

        const int wn1b = (wid >> 1) * 64;
#pragma unroll
        for (int mi = 0; mi < 4; mi++)
#pragma unroll
            for (int nj = 0; nj < 8; nj++) {
                int r0 = wm + mi * 16 + (lane >> 2);
                int n0 = wn1b + nj * 8 + (lane & 3) * 2;
                float g0 = gelu_f(acc1[mi][nj][0]);
                float g1 = gelu_f(acc1[mi][nj][1]);
                float g2 = gelu_f(acc1[mi][nj][2]);
                float g3 = gelu_f(acc1[mi][nj][3]);
                __half h0 = __float2half_rn(g0), h1 = __float2half_rn(g1);
                __half h2 = __float2half_rn(g2), h3 = __float2half_rn(g3);
                uint32_t hi0 = (uint32_t)__half_as_ushort(h0) |
                               ((uint32_t)__half_as_ushort(h1) << 16);
                uint32_t hi1 = (uint32_t)__half_as_ushort(h2) |
                               ((uint32_t)__half_as_ushort(h3) << 16);
                uint32_t lo0 = pack_h2(g0 - __half2float(h0), g1 - __half2float(h1));
                uint32_t lo1 = pack_h2(g2 - __half2float(h2), g3 - __half2float(h3));
                int ch = n0 >> 3, within = (n0 & 7) * 2;
                int ph = (ch & ~7) | ((ch & 7) ^ (r0 & 7));
                char* base0 = smem + r0 * 1024 + within;
                char* base1 = smem + (r0 + 8) * 1024 + within;
                *(uint32_t*)(base0 + ph * 16) = hi0;
                *(uint32_t*)(base0 + (ph + 32) * 16) = lo0;
                *(uint32_t*)(base1 + ph * 16) = hi1;
                *(uint32_t*)(base1 + (ph + 32) * 16) = lo1;
            }
    }
    __syncthreads();

    // Phase 2: delta[128x64], warp tile 64x16, K'=512
    float acc2[4][2][4] = {};
    const int wn2 = (wid >> 1) * 16;
#pragma unroll
    for (int ks = 0; ks < 32; ks++) {
        uint32_t afr[4][4];
#pragma unroll
        for (int mi = 0; mi < 4; mi++) {
            int rr = wm + mi * 16 + (lane & 15);
            int cu = ks * 2 + (lane >> 4);
            int ph = (cu & ~7) | ((cu & 7) ^ (rr & 7));
            ldsm4(afr[mi], HS + rr * 1024 + ph * 16);
        }
        uint32_t bfr[4];
        {
            int rr = wn2 + (lane & 7) + ((lane >> 4) * 8);
            int cu = (ks * 2 + ((lane >> 3) & 1)) & 31;
            int ph = (cu & ~7) | ((cu & 7) ^ (rr & 7));
            ldsm4(bfr, W2S + rr * 512 + ph * 16);
        }
#pragma unroll
        for (int mi = 0; mi < 4; mi++)
#pragma unroll
            for (int nj = 0; nj < 2; nj++)
                mma16816(acc2[mi][nj], afr[mi], bfr[nj * 2], bfr[nj * 2 + 1]);
    }

    // Epilogue: xb += lam * delta
#pragma unroll
    for (int mi = 0; mi < 4; mi++)
#pragma unroll
        for (int nj = 0; nj < 2; nj++) {
            int r0 = wm + mi * 16 + (lane >> 2);
            int n0 = wn2 + nj * 8 + (lane & 3) * 2;
#pragma unroll
            for (int h = 0; h < 2; h++) {
                int g = rt * 128 + r0 + h * 8;
                float* p = xb + ((size_t)(g >> 2) * 32 + t * 4 + (g & 3)) * 64 + n0;
                float2 old = *(float2*)p;
                old.x += lam * acc2[mi][nj][h * 2 + 0];
                old.y += lam * acc2[mi][nj][h * 2 + 1];
                *(float2*)p = old;
            }
        }
}

// ---------------------------------------------------------------------------
// Embedding gather + pos add
// ---------------------------------------------------------------------------
__global__ void embed_kernel(const int* __restrict__ ids,
                             const float* __restrict__ emb,
                             const float* __restrict__ pos,
                             float* __restrict__ x) {
    int s = blockIdx.x;
    int q = threadIdx.x;
    int id = ids[s];
    float4 e = ((const float4*)(emb + (size_t)id * D_DIM))[q];
    float4 p = ((const float4*)(pos + (size_t)(s & 1023) * D_DIM))[q];
    float4 o;
    o.x = e.x + p.x; o.y = e.y + p.y; o.z = e.z + p.z; o.w = e.w + p.w;
    ((float4*)(x + (size_t)s * D_DIM))[q] = o;
}

// ---------------------------------------------------------------------------
// LayerNorm (in place)
// ---------------------------------------------------------------------------
__global__ void ln_kernel(float* __restrict__ x, const float* __restrict__ g,
                          const float* __restrict__ b) {
    __shared__ float red[256];
    const int s = blockIdx.x, tid = threadIdx.x;
    float4* row = (float4*)(x + (size_t)s * D_DIM);
    float4 v = row[tid];
    red[tid] = v.x + v.y + v.z + v.w;
    __syncthreads();
    for (int o = 128; o > 0; o >>= 1) {
        if (tid < o) red[tid] += red[tid + o];
        __syncthreads();
    }
    float mu = red[0] * (1.0f / 1024.0f);
    __syncthreads();
    float dx = v.x - mu, dy = v.y - mu, dz = v.z - mu, dw = v.w - mu;
    red[tid] = dx * dx + dy * dy + dz * dz + dw * dw;
    __syncthreads();
    for (int o = 128; o > 0; o >>= 1) {
        if (tid < o) red[tid] += red[tid + o];
        __syncthreads();
    }
    float rstd = rsqrtf(red[0] * (1.0f / 1024.0f) + 1e-5f);
    float4 gg = ((const float4*)g)[tid];
    float4 bb = ((const float4*)b)[tid];
    float4 o4;
    o4.x = dx * rstd * gg.x + bb.x;
    o4.y = dy * rstd * gg.y + bb.y;
    o4.z = dz * rstd * gg.z + bb.z;
    o4.w = dw * rstd * gg.w + bb.w;
    row[tid] = o4;
}

// ---------------------------------------------------------------------------
// Deterministic aux reduction
// ---------------------------------------------------------------------------
__global__ void aux_kernel(const float* __restrict__ pcm, float* __restrict__ out) {
    __shared__ float red[256];
    const int tid = threadIdx.x;
    float s = 0.0f;
    for (int i = tid; i < 2 * S_TOT * NB; i += 256) s += pcm[i];
    red[tid] = s;
    __syncthreads();
    for (int o = 128; o > 0; o >>= 1) {
        if (tid < o) red[tid] += red[tid + o];
        __syncthreads();
    }
    if (tid == 0) out[0] = 0.1f * red[0] / 262144.0f;
}

// ---------------------------------------------------------------------------
extern "C" void kernel_launch(void* const* d_in, const int* in_sizes, int n_in,
                              void* d_out, int out_size) {
    const int*   ids  = (const int*)d_in[0];
    const float* emb  = (const float*)d_in[1];
    const float* pos  = (const float*)d_in[2];
    const float* fo_w = (const float*)d_in[3];
    const float* fo_b = (const float*)d_in[4];
    const float* W1   = (const float*)d_in[5];
    const float* W2   = (const float*)d_in[6];
    const float* Wz   = (const float*)d_in[7];
    const float* fi_w = (const float*)d_in[8];
    const float* fi_b = (const float*)d_in[9];
    const float* ln_g = (const float*)d_in[10];
    const float* ln_b = (const float*)d_in[11];
    const float* lamp = (const float*)d_in[12];
    float* out = (float*)d_out;

    float *x, *xb, *zhat, *pcm;
    __half *Ah, *Bh, *Axo, *Bfo, *Axi, *Bfi, *W1p, *W2p;
    cudaGetSymbolAddress((void**)&x,    g_x);
    cudaGetSymbolAddress((void**)&xb,   g_xb);
    cudaGetSymbolAddress((void**)&zhat, g_zhat);
    cudaGetSymbolAddress((void**)&pcm,  g_pcm);
    cudaGetSymbolAddress((void**)&Ah,   g_Ah);
    cudaGetSymbolAddress((void**)&Bh,   g_Bh);
    cudaGetSymbolAddress((void**)&Axo,  g_Axo);
    cudaGetSymbolAddress((void**)&Bfo,  g_Bfo);
    cudaGetSymbolAddress((void**)&Axi,  g_Axi);
    cudaGetSymbolAddress((void**)&Bfi,  g_Bfi);
    cudaGetSymbolAddress((void**)&W1p,  g_W1p);
    cudaGetSymbolAddress((void**)&W2p,  g_W2p);

    cudaFuncSetAttribute(gemm_hmma, cudaFuncAttributeMaxDynamicSharedMemorySize,
                         HSMEM);
    cudaFuncSetAttribute(mlp_tc, cudaFuncAttributeMaxDynamicSharedMemorySize,
                         MLPTC_SMEM);

    // 1. embed + weight conversions
    embed_kernel<<<S_TOT, 256>>>(ids, emb, pos, x);
    convB_h<<<V_DIM, 256>>>(emb, Bh);
    convB3T<<<dim3(D_DIM / 32, T_DIM / 32), 256>>>(fo_w, Bfo, D_DIM, T_DIM);
    convB3T<<<dim3(T_DIM / 32, D_DIM / 32), 256>>>(fi_w, Bfi, T_DIM, D_DIM);
    convW1p<<<512, 256>>>(W1, W1p);
    convW2p<<<512, 256>>>(W2, W2p);

    // 2. fan_out (HMMA 3-term)
    convA3<<<S_TOT, 256>>>(x, Axo, D_DIM);
    gemm_hmma<<<dim3(S_TOT / 128, T_DIM / 128), 256, HSMEM>>>(
        Axo, Bfo, fo_b, xb, 3 * D_DIM, 3 * D_DIM, T_DIM, 3 * D_DIM / 64, ~0);

    // 3. refine passes (fused z-pass + MLP on tensor cores)
    for (int r = 0; r < 3; r++) {
        mlp_tc<<<dim3(128, NB), 256, MLPTC_SMEM>>>(xb, W1p, W2p, Wz, zhat, pcm,
                                                   lamp, r);
    }

    // 4. fan_in (HMMA 3-term)
    convA3<<<S_TOT, 256>>>(xb, Axi, T_DIM);
    gemm_hmma<<<dim3(S_TOT / 128, D_DIM / 128), 256, HSMEM>>>(
        Axi, Bfi, fi_b, x, 3 * T_DIM, 3 * T_DIM, D_DIM, 3 * T_DIM / 64, ~0);

    // 5. layernorm
    ln_kernel<<<S_TOT, 256>>>(x, ln_g, ln_b);

    // 6. logits (HMMA plain fp16 A, K=1024, 128x128 tile)
    convA_h<<<S_TOT * 1024 / 1024, 256>>>(x, Ah);
    gemm_hmma<<<dim3(S_TOT / 128, V_DIM / 128), 256, HSMEM>>>(
        Ah, Bh, (const float*)0, out, 1024, 1024, V_DIM, 16, ~0);

    // 7. aux loss
    if (out_size > S_TOT * V_DIM) {
        aux_kernel<<<1, 256>>>(pcm, out + (size_t)S_TOT * V_DIM);
    }
}

// round 10
// speedup vs baseline: 1.6807x; 1.1152x over previous
#include <cuda_runtime.h>
#include <cuda_fp16.h>
#include <stdint.h>
#include <math.h>

// Problem dims
#define S_TOT 4096     // BS*N
#define D_DIM 1024
#define T_DIM 2048
#define V_DIM 32000
#define NB 8

// Scratch (device globals — allocation-free rule)
__device__ float g_x[S_TOT * D_DIM];
__device__ float g_xb[S_TOT * T_DIM];
__device__ float g_zhat[S_TOT * NB * 64];
__device__ float g_pcm[2 * S_TOT * NB];
__device__ __half g_Ah[(size_t)S_TOT * 1024];    // logits A plain fp16
__device__ __half g_Bh[(size_t)V_DIM * 1024];    // emb fp16
__device__ __half g_Axo[(size_t)S_TOT * 2048];   // fan_out A 2-term (hi|lo)
__device__ __half g_Bfo[(size_t)T_DIM * 1024];   // fo_w^T plain fp16
__device__ __half g_Axi[(size_t)S_TOT * 4096];   // fan_in A 2-term
__device__ __half g_Bfi[(size_t)D_DIM * 2048];   // fi_w^T plain fp16
__device__ __half g_W1p[NB * 256 * 64];
__device__ __half g_W2p[NB * 64 * 256];

__device__ __forceinline__ uint32_t smem_u32(const void* p) {
    uint32_t a;
    asm("{ .reg .u64 t; cvta.to.shared.u64 t, %1; cvt.u32.u64 %0, t; }"
        : "=r"(a) : "l"(p));
    return a;
}
__device__ __forceinline__ void ldsm4(uint32_t* r, uint32_t addr) {
    asm volatile("ldmatrix.sync.aligned.m8n8.x4.shared.b16 {%0,%1,%2,%3}, [%4];"
                 : "=r"(r[0]), "=r"(r[1]), "=r"(r[2]), "=r"(r[3]) : "r"(addr));
}
__device__ __forceinline__ void mma16816(float* c, const uint32_t* a,
                                         uint32_t b0, uint32_t b1) {
    asm volatile(
        "mma.sync.aligned.m16n8k16.row.col.f32.f16.f16.f32 "
        "{%0,%1,%2,%3}, {%4,%5,%6,%7}, {%8,%9}, {%0,%1,%2,%3};"
        : "+f"(c[0]), "+f"(c[1]), "+f"(c[2]), "+f"(c[3])
        : "r"(a[0]), "r"(a[1]), "r"(a[2]), "r"(a[3]), "r"(b0), "r"(b1));
}
__device__ __forceinline__ float gelu_f(float v) {
    float u = 0.7978845608028654f * (v + 0.044715f * v * v * v);
    float th;
    asm("tanh.approx.f32 %0, %1;" : "=f"(th) : "f"(u));
    return 0.5f * v * (1.0f + th);
}
__device__ __forceinline__ uint32_t pack_h2(float a, float b) {
    __half ha = __float2half_rn(a), hb = __float2half_rn(b);
    return (uint32_t)__half_as_ushort(ha) | ((uint32_t)__half_as_ushort(hb) << 16);
}

// ---------------------------------------------------------------------------
// Conversions
// ---------------------------------------------------------------------------
// plain fp16 row copy (logits A and B): src f32 -> dst fp16, linear
__global__ void conv_h(const float* __restrict__ src, __half* __restrict__ dst) {
    size_t i = (size_t)blockIdx.x * 256 + threadIdx.x;
    float4 v = ((const float4*)src)[i];
    uint2 H;
    H.x = pack_h2(v.x, v.y); H.y = pack_h2(v.z, v.w);
    ((uint2*)dst)[i] = H;
}

// A 2-term (hi | lo): src [rows, K] f32 -> dst [rows, 2K] fp16
__global__ void convA2(const float* __restrict__ src, __half* __restrict__ dst,
                       int K) {
    int row = blockIdx.x;
    const float4* sp = (const float4*)(src + (size_t)row * K);
    __half* base = dst + (size_t)row * 2 * K;
    for (int q = threadIdx.x; q < K / 4; q += 256) {
        float4 v = sp[q];
        __half h0 = __float2half_rn(v.x), h1 = __float2half_rn(v.y);
        __half h2 = __float2half_rn(v.z), h3 = __float2half_rn(v.w);
        uint2 H, L;
        H.x = pack_h2(v.x, v.y); H.y = pack_h2(v.z, v.w);
        L.x = pack_h2(v.x - __half2float(h0), v.y - __half2float(h1));
        L.y = pack_h2(v.z - __half2float(h2), v.w - __half2float(h3));
        *(uint2*)(base + q * 4)     = H;
        *(uint2*)(base + K + q * 4) = L;
    }
}

// B transpose + plain fp16: src [K,N] row-major -> dst [N,K]
__global__ void convBT(const float* __restrict__ src, __half* __restrict__ dst,
                       int K, int N) {
    __shared__ float tile[32][33];
    int k0 = blockIdx.x * 32, n0 = blockIdx.y * 32;
    int tx = threadIdx.x & 31, ty = threadIdx.x >> 5;
    for (int i = ty; i < 32; i += 8)
        tile[i][tx] = src[(size_t)(k0 + i) * N + n0 + tx];
    __syncthreads();
    for (int i = ty; i < 32; i += 8) {
        int n = n0 + i;
        dst[(size_t)n * K + k0 + tx] = __float2half_rn(tile[tx][i]);
    }
}

// Pre-swizzled fp16 weights for mlp_tc
__global__ void convW1p(const float* __restrict__ W1, __half* __restrict__ W1p) {
    int idx = blockIdx.x * 256 + threadIdx.x;
    int t = idx >> 14, rem = idx & 16383;
    int rr = rem >> 6, ph = (rem >> 3) & 7, j = rem & 7;
    int k = ((ph ^ (rr & 7)) << 3) | j;
    W1p[idx] = __float2half_rn(W1[((size_t)t * 64 + k) * 256 + rr]);
}
__global__ void convW2p(const float* __restrict__ W2, __half* __restrict__ W2p) {
    int idx = blockIdx.x * 256 + threadIdx.x;
    int t = idx >> 14, rem = idx & 16383;
    int rr = rem >> 8, ph = (rem >> 3) & 31, j = rem & 7;
    int c = (ph & ~7) | ((ph & 7) ^ (rr & 7));
    int k = (c << 3) | j;
    W2p[idx] = __float2half_rn(W2[((size_t)t * 256 + k) * 64 + rr]);
}

// ---------------------------------------------------------------------------
// HMMA fp16 GEMM, 128x128 tile (fan_out / fan_in / logits)
// ---------------------------------------------------------------------------
#define HBUF 32768
#define HSMEM (2 * HBUF)

__global__ __launch_bounds__(256) void gemm_hmma(
    const __half* __restrict__ A, const __half* __restrict__ B,
    const float* __restrict__ bias, float* __restrict__ C,
    int ldA, int ldB, int N, int nch, int bkmask) {
    extern __shared__ __align__(128) char smem[];
    const uint32_t sb = smem_u32(smem);
    const int tid = threadIdx.x, lane = tid & 31, wid = tid >> 5;
    const int bm = blockIdx.x * 128, bn = blockIdx.y * 128;
    const int wm = (wid & 1) * 64, wn = (wid >> 1) * 32;

    float acc[4][4][4] = {};

    auto issue = [&](int ch, int buf) {
        int k0 = ch * 64;
        int bk = k0 & bkmask;
        uint32_t abase = sb + buf * HBUF;
        uint32_t bbase = abase + 16384;
#pragma unroll
        for (int i = 0; i < 4; i++) {
            int idx = tid + 256 * i;
            int r = idx >> 3, c = idx & 7;
            uint32_t off = (uint32_t)(r * 128 + ((c ^ (r & 7)) * 16));
            const __half* gp = A + (size_t)(bm + r) * ldA + k0 + c * 8;
            asm volatile("cp.async.cg.shared.global [%0], [%1], 16;"
                         :: "r"(abase + off), "l"(gp));
        }
#pragma unroll
        for (int i = 0; i < 4; i++) {
            int idx = tid + 256 * i;
            int r = idx >> 3, c = idx & 7;
            uint32_t off = (uint32_t)(r * 128 + ((c ^ (r & 7)) * 16));
            const __half* gp = B + (size_t)(bn + r) * ldB + bk + c * 8;
            asm volatile("cp.async.cg.shared.global [%0], [%1], 16;"
                         :: "r"(bbase + off), "l"(gp));
        }
        asm volatile("cp.async.commit_group;" ::: "memory");
    };

    issue(0, 0);

    for (int ch = 0; ch < nch; ch++) {
        int b = ch & 1;
        if (ch + 1 < nch) {
            issue(ch + 1, b ^ 1);
            asm volatile("cp.async.wait_group 1;" ::: "memory");
        } else {
            asm volatile("cp.async.wait_group 0;" ::: "memory");
        }
        __syncthreads();

        uint32_t abase = sb + b * HBUF;
        uint32_t bbase = abase + 16384;
#pragma unroll
        for (int ks = 0; ks < 4; ks++) {
            uint32_t afr[4][4];
#pragma unroll
            for (int mi = 0; mi < 4; mi++) {
                int r = wm + mi * 16 + (lane & 15);
                int cu = ks * 2 + (lane >> 4);
                uint32_t addr = abase + r * 128 + ((cu ^ (r & 7)) * 16);
                ldsm4(afr[mi], addr);
            }
            uint32_t bfr[2][4];
#pragma unroll
            for (int p = 0; p < 2; p++) {
                int r = wn + p * 16 + (lane & 7) + ((lane >> 4) * 8);
                int cu = ks * 2 + ((lane >> 3) & 1);
                uint32_t addr = bbase + r * 128 + ((cu ^ (r & 7)) * 16);
                ldsm4(bfr[p], addr);
            }
#pragma unroll
            for (int mi = 0; mi < 4; mi++)
#pragma unroll
                for (int nj = 0; nj < 4; nj++)
                    mma16816(acc[mi][nj], afr[mi],
                             bfr[nj >> 1][(nj & 1) * 2 + 0],
                             bfr[nj >> 1][(nj & 1) * 2 + 1]);
        }
        __syncthreads();
    }

#pragma unroll
    for (int mi = 0; mi < 4; mi++) {
#pragma unroll
        for (int nj = 0; nj < 4; nj++) {
            int row = bm + wm + mi * 16 + (lane >> 2);
            int col = bn + wn + nj * 8 + (lane & 3) * 2;
            float b0 = bias ? bias[col] : 0.0f;
            float b1 = bias ? bias[col + 1] : 0.0f;
            float2 v0 = make_float2(acc[mi][nj][0] + b0, acc[mi][nj][1] + b1);
            float2 v1 = make_float2(acc[mi][nj][2] + b0, acc[mi][nj][3] + b1);
            *(float2*)(C + (size_t)row * N + col) = v0;
            *(float2*)(C + (size_t)(row + 8) * N + col) = v1;
        }
    }
}

// ---------------------------------------------------------------------------
// Fused HMMA refine MLP + z-pass. Phase2 uses PLAIN fp16 H (K'=256).
// Smem: XS 0..32K + W1S 32..64K (phase1); HS 0..64K (phase2, reuse);
//       W2S 64..96K; WZS 96..112K (fp32 Wz[t]); ZS 112..120K (fp32 z[32][64]).
// ---------------------------------------------------------------------------
#define MLPTC_SMEM (122880)
__global__ __launch_bounds__(256) void mlp_tc(
    float* __restrict__ xb, const __half* __restrict__ W1p,
    const __half* __restrict__ W2p, const float* __restrict__ Wz,
    float* __restrict__ zhat, float* __restrict__ pcm,
    const float* __restrict__ lam_logit, int r) {
    extern __shared__ __align__(128) char smem[];
    const uint32_t sb = smem_u32(smem);
    const uint32_t XS = sb, W1S = sb + 32768, HS = sb, W2S = sb + 65536;
    const uint32_t WZS = sb + 98304;
    float* wzsp = (float*)(smem + 98304);
    float* zsp = (float*)(smem + 114688);
    const int tid = threadIdx.x, lane = tid & 31, wid = tid >> 5;
    const int t = blockIdx.y, rt = blockIdx.x;
    const int wm = (wid & 1) * 64;
    float lam = 1.0f;
    if (r > 0) lam = 1.0f / (1.0f + expf(-lam_logit[0]));

    // async-load weights: W1p, W2p (pre-swizzled fp16), Wz (fp32)
    {
        const __half* w1g = W1p + (size_t)t * 16384;
        const __half* w2g = W2p + (size_t)t * 16384;
        const float* wzg = Wz + (size_t)t * 4096;
#pragma unroll
        for (int i = 0; i < 8; i++) {
            int idx = tid + 256 * i;
            asm volatile("cp.async.cg.shared.global [%0], [%1], 16;"
                         :: "r"(W1S + idx * 16), "l"(w1g + idx * 8));
        }
#pragma unroll
        for (int i = 0; i < 8; i++) {
            int idx = tid + 256 * i;
            asm volatile("cp.async.cg.shared.global [%0], [%1], 16;"
                         :: "r"(W2S + idx * 16), "l"(w2g + idx * 8));
        }
#pragma unroll
        for (int i = 0; i < 4; i++) {
            int idx = tid + 256 * i;
            asm volatile("cp.async.cg.shared.global [%0], [%1], 16;"
                         :: "r"(WZS + idx * 16), "l"(wzg + idx * 4));
        }
        asm volatile("cp.async.commit_group;" ::: "memory");
    }

    // X tile: load fp32, split hi/lo fp16 into XS (row stride 256B, swizzled)
#pragma unroll
    for (int i = 0; i < 4; i++) {
        int idx = tid + 256 * i;
        int lr = idx >> 3, c = idx & 7;
        int g = rt * 128 + lr;
        const float* xp = xb + ((size_t)(g >> 2) * 32 + t * 4 + (g & 3)) * 64 + c * 8;
        float4 v0 = *(const float4*)xp;
        float4 v1 = *(const float4*)(xp + 4);
        float vv[8] = {v0.x, v0.y, v0.z, v0.w, v1.x, v1.y, v1.z, v1.w};
        uint4 Hh, Ll;
        uint32_t* hw = (uint32_t*)&Hh;
        uint32_t* lw = (uint32_t*)&Ll;
#pragma unroll
        for (int j = 0; j < 4; j++) {
            float a = vv[2 * j], b = vv[2 * j + 1];
            __half ha = __float2half_rn(a), hb = __float2half_rn(b);
            hw[j] = (uint32_t)__half_as_ushort(ha) |
                    ((uint32_t)__half_as_ushort(hb) << 16);
            lw[j] = pack_h2(a - __half2float(ha), b - __half2float(hb));
        }
        int phh = c ^ (lr & 7);
        *(uint4*)(smem + lr * 256 + phh * 16) = Hh;
        *(uint4*)(smem + lr * 256 + (8 + phh) * 16) = Ll;
    }
    __syncthreads();  // XS visible

    // z = mean_c (hi+lo reconstruction ~fp32-exact)
    {
        int s_loc = tid >> 3;
        int d0 = (tid & 7) * 8;
        float zv[8] = {};
#pragma unroll
        for (int c = 0; c < 4; c++) {
            int lr = s_loc * 4 + c;
            int byte_off = lr * 256 + (((d0 >> 3) ^ (lr & 7)) * 16);
            uint4 hi = *(const uint4*)(smem + byte_off);
            uint4 lo = *(const uint4*)(smem + byte_off + 128);
            const __half2* hp = (const __half2*)&hi;
            const __half2* lp = (const __half2*)&lo;
#pragma unroll
            for (int j = 0; j < 4; j++) {
                float2 h2 = __half22float2(hp[j]);
                float2 l2 = __half22float2(lp[j]);
                zv[2 * j]     += h2.x + l2.x;
                zv[2 * j + 1] += h2.y + l2.y;
            }
        }
#pragma unroll
        for (int j = 0; j < 8; j++) zsp[s_loc * 64 + d0 + j] = 0.25f * zv[j];
    }
    asm volatile("cp.async.wait_group 0;" ::: "memory");  // weights in
    __syncthreads();  // ZS + weights visible

    // pcm (r>0) + zhat = z @ Wz[t]
    {
        int s_loc = tid >> 3, e0 = (tid & 7) * 8;
        int st = (rt * 32 + s_loc) * 8 + t;
        const float* zr = zsp + s_loc * 64;
        float acc[8] = {};
        for (int d = 0; d < 64; d++) {
            float zv = zr[d];
            const float* wr = wzsp + d * 64 + e0;
#pragma unroll
            for (int j = 0; j < 8; j++) acc[j] = fmaf(zv, wr[j], acc[j]);
        }
        if (r > 0) {
            float sq = 0.0f;
#pragma unroll
            for (int j = 0; j < 8; j++) {
                float diff = zhat[(size_t)st * 64 + e0 + j] - zr[e0 + j];
                sq = fmaf(diff, diff, sq);
            }
            sq += __shfl_down_sync(0xffffffffu, sq, 4, 8);
            sq += __shfl_down_sync(0xffffffffu, sq, 2, 8);
            sq += __shfl_down_sync(0xffffffffu, sq, 1, 8);
            if ((tid & 7) == 0)
                pcm[(size_t)(r - 1) * (S_TOT * NB) + st] = sq;
        }
#pragma unroll
        for (int j = 0; j < 8; j++) zhat[(size_t)st * 64 + e0 + j] = acc[j];
    }

    // Phase 1: H[128x256] = gelu(X2 @ W1h), warp tile 64x64
    float acc1[4][8][4] = {};
    {
        const int wn1 = (wid >> 1) * 64;
#pragma unroll
        for (int ks = 0; ks < 8; ks++) {
            uint32_t afr[4][4];
#pragma unroll
            for (int mi = 0; mi < 4; mi++) {
                int rr = wm + mi * 16 + (lane & 15);
                int cu = ks * 2 + (lane >> 4);
                int ph = (cu & 8) | ((cu & 7) ^ (rr & 7));
                ldsm4(afr[mi], XS + rr * 256 + ph * 16);
            }
            uint32_t bfr[4][4];
#pragma unroll
            for (int p = 0; p < 4; p++) {
                int rr = wn1 + p * 16 + (lane & 7) + ((lane >> 4) * 8);
                int cu = (ks * 2 + ((lane >> 3) & 1)) & 7;
                int ph = cu ^ (rr & 7);
                ldsm4(bfr[p], W1S + rr * 128 + ph * 16);
            }
#pragma unroll
            for (int mi = 0; mi < 4; mi++)
#pragma unroll
                for (int nj = 0; nj < 8; nj++)
                    mma16816(acc1[mi][nj], afr[mi],
                             bfr[nj >> 1][(nj & 1) * 2 + 0],
                             bfr[nj >> 1][(nj & 1) * 2 + 1]);
        }
        __syncthreads();  // phase1 smem reads done (XS/W1S free)

        // gelu + PLAIN fp16 store into HS (row stride 512B, chunks 0..31)
        const int wn1b = (wid >> 1) * 64;
#pragma unroll
        for (int mi = 0; mi < 4; mi++)
#pragma unroll
            for (int nj = 0; nj < 8; nj++) {
                int r0 = wm + mi * 16 + (lane >> 2);
                int n0 = wn1b + nj * 8 + (lane & 3) * 2;
                float g0 = gelu_f(acc1[mi][nj][0]);
                float g1 = gelu_f(acc1[mi][nj][1]);
                float g2 = gelu_f(acc1[mi][nj][2]);
                float g3 = gelu_f(acc1[mi][nj][3]);
                uint32_t hi0 = pack_h2(g0, g1);
                uint32_t hi1 = pack_h2(g2, g3);
                int ch = n0 >> 3, within = (n0 & 7) * 2;
                int ph0 = (ch & ~7) | ((ch & 7) ^ (r0 & 7));
                int ph1 = (ch & ~7) | ((ch & 7) ^ ((r0 + 8) & 7));
                *(uint32_t*)(smem + r0 * 512 + ph0 * 16 + within) = hi0;
                *(uint32_t*)(smem + (r0 + 8) * 512 + ph1 * 16 + within) = hi1;
            }
    }
    __syncthreads();

    // Phase 2: delta[128x64] = H @ W2h, warp tile 64x16, K'=256
    float acc2[4][2][4] = {};
    const int wn2 = (wid >> 1) * 16;
#pragma unroll
    for (int ks = 0; ks < 16; ks++) {
        uint32_t afr[4][4];
#pragma unroll
        for (int mi = 0; mi < 4; mi++) {
            int rr = wm + mi * 16 + (lane & 15);
            int cu = ks * 2 + (lane >> 4);
            int ph = (cu & ~7) | ((cu & 7) ^ (rr & 7));
            ldsm4(afr[mi], HS + rr * 512 + ph * 16);
        }
        uint32_t bfr[4];
        {
            int rr = wn2 + (lane & 7) + ((lane >> 4) * 8);
            int cu = ks * 2 + ((lane >> 3) & 1);
            int ph = (cu & ~7) | ((cu & 7) ^ (rr & 7));
            ldsm4(bfr, W2S + rr * 512 + ph * 16);
        }
#pragma unroll
        for (int mi = 0; mi < 4; mi++)
#pragma unroll
            for (int nj = 0; nj < 2; nj++)
                mma16816(acc2[mi][nj], afr[mi], bfr[nj * 2], bfr[nj * 2 + 1]);
    }

    // Epilogue: xb += lam * delta
#pragma unroll
    for (int mi = 0; mi < 4; mi++)
#pragma unroll
        for (int nj = 0; nj < 2; nj++) {
            int r0 = wm + mi * 16 + (lane >> 2);
            int n0 = wn2 + nj * 8 + (lane & 3) * 2;
#pragma unroll
            for (int h = 0; h < 2; h++) {
                int g = rt * 128 + r0 + h * 8;
                float* p = xb + ((size_t)(g >> 2) * 32 + t * 4 + (g & 3)) * 64 + n0;
                float2 old = *(float2*)p;
                old.x += lam * acc2[mi][nj][h * 2 + 0];
                old.y += lam * acc2[mi][nj][h * 2 + 1];
                *(float2*)p = old;
            }
        }
}

// ---------------------------------------------------------------------------
// Embedding gather + pos add
// ---------------------------------------------------------------------------
__global__ void embed_kernel(const int* __restrict__ ids,
                             const float* __restrict__ emb,
                             const float* __restrict__ pos,
                             float* __restrict__ x) {
    int s = blockIdx.x;
    int q = threadIdx.x;
    int id = ids[s];
    float4 e = ((const float4*)(emb + (size_t)id * D_DIM))[q];
    float4 p = ((const float4*)(pos + (size_t)(s & 1023) * D_DIM))[q];
    float4 o;
    o.x = e.x + p.x; o.y = e.y + p.y; o.z = e.z + p.z; o.w = e.w + p.w;
    ((float4*)(x + (size_t)s * D_DIM))[q] = o;
}

// ---------------------------------------------------------------------------
// LayerNorm (in place)
// ---------------------------------------------------------------------------
__global__ void ln_kernel(float* __restrict__ x, const float* __restrict__ g,
                          const float* __restrict__ b) {
    __shared__ float red[256];
    const int s = blockIdx.x, tid = threadIdx.x;
    float4* row = (float4*)(x + (size_t)s * D_DIM);
    float4 v = row[tid];
    red[tid] = v.x + v.y + v.z + v.w;
    __syncthreads();
    for (int o = 128; o > 0; o >>= 1) {
        if (tid < o) red[tid] += red[tid + o];
        __syncthreads();
    }
    float mu = red[0] * (1.0f / 1024.0f);
    __syncthreads();
    float dx = v.x - mu, dy = v.y - mu, dz = v.z - mu, dw = v.w - mu;
    red[tid] = dx * dx + dy * dy + dz * dz + dw * dw;
    __syncthreads();
    for (int o = 128; o > 0; o >>= 1) {
        if (tid < o) red[tid] += red[tid + o];
        __syncthreads();
    }
    float rstd = rsqrtf(red[0] * (1.0f / 1024.0f) + 1e-5f);
    float4 gg = ((const float4*)g)[tid];
    float4 bb = ((const float4*)b)[tid];
    float4 o4;
    o4.x = dx * rstd * gg.x + bb.x;
    o4.y = dy * rstd * gg.y + bb.y;
    o4.z = dz * rstd * gg.z + bb.z;
    o4.w = dw * rstd * gg.w + bb.w;
    row[tid] = o4;
}

// ---------------------------------------------------------------------------
// Deterministic aux reduction
// ---------------------------------------------------------------------------
__global__ void aux_kernel(const float* __restrict__ pcm, float* __restrict__ out) {
    __shared__ float red[256];
    const int tid = threadIdx.x;
    float s = 0.0f;
    for (int i = tid; i < 2 * S_TOT * NB; i += 256) s += pcm[i];
    red[tid] = s;
    __syncthreads();
    for (int o = 128; o > 0; o >>= 1) {
        if (tid < o) red[tid] += red[tid + o];
        __syncthreads();
    }
    if (tid == 0) out[0] = 0.1f * red[0] / 262144.0f;
}

// ---------------------------------------------------------------------------
extern "C" void kernel_launch(void* const* d_in, const int* in_sizes, int n_in,
                              void* d_out, int out_size) {
    const int*   ids  = (const int*)d_in[0];
    const float* emb  = (const float*)d_in[1];
    const float* pos  = (const float*)d_in[2];
    const float* fo_w = (const float*)d_in[3];
    const float* fo_b = (const float*)d_in[4];
    const float* W1   = (const float*)d_in[5];
    const float* W2   = (const float*)d_in[6];
    const float* Wz   = (const float*)d_in[7];
    const float* fi_w = (const float*)d_in[8];
    const float* fi_b = (const float*)d_in[9];
    const float* ln_g = (const float*)d_in[10];
    const float* ln_b = (const float*)d_in[11];
    const float* lamp = (const float*)d_in[12];
    float* out = (float*)d_out;

    float *x, *xb, *zhat, *pcm;
    __half *Ah, *Bh, *Axo, *Bfo, *Axi, *Bfi, *W1p, *W2p;
    cudaGetSymbolAddress((void**)&x,    g_x);
    cudaGetSymbolAddress((void**)&xb,   g_xb);
    cudaGetSymbolAddress((void**)&zhat, g_zhat);
    cudaGetSymbolAddress((void**)&pcm,  g_pcm);
    cudaGetSymbolAddress((void**)&Ah,   g_Ah);
    cudaGetSymbolAddress((void**)&Bh,   g_Bh);
    cudaGetSymbolAddress((void**)&Axo,  g_Axo);
    cudaGetSymbolAddress((void**)&Bfo,  g_Bfo);
    cudaGetSymbolAddress((void**)&Axi,  g_Axi);
    cudaGetSymbolAddress((void**)&Bfi,  g_Bfi);
    cudaGetSymbolAddress((void**)&W1p,  g_W1p);
    cudaGetSymbolAddress((void**)&W2p,  g_W2p);

    cudaFuncSetAttribute(gemm_hmma, cudaFuncAttributeMaxDynamicSharedMemorySize,
                         HSMEM);
    cudaFuncSetAttribute(mlp_tc, cudaFuncAttributeMaxDynamicSharedMemorySize,
                         MLPTC_SMEM);

    // 1. embed + weight conversions
    embed_kernel<<<S_TOT, 256>>>(ids, emb, pos, x);
    conv_h<<<V_DIM, 256>>>(emb, Bh);                               // 32000x1024
    convBT<<<dim3(D_DIM / 32, T_DIM / 32), 256>>>(fo_w, Bfo, D_DIM, T_DIM);
    convBT<<<dim3(T_DIM / 32, D_DIM / 32), 256>>>(fi_w, Bfi, T_DIM, D_DIM);
    convW1p<<<512, 256>>>(W1, W1p);
    convW2p<<<512, 256>>>(W2, W2p);

    // 2. fan_out (HMMA 2-term A, plain B with k-wrap)
    convA2<<<S_TOT, 256>>>(x, Axo, D_DIM);
    gemm_hmma<<<dim3(S_TOT / 128, T_DIM / 128), 256, HSMEM>>>(
        Axo, Bfo, fo_b, xb, 2 * D_DIM, D_DIM, T_DIM, 2 * D_DIM / 64, D_DIM - 1);

    // 3. refine passes (fused z-pass + MLP on tensor cores)
    for (int r = 0; r < 3; r++) {
        mlp_tc<<<dim3(128, NB), 256, MLPTC_SMEM>>>(xb, W1p, W2p, Wz, zhat, pcm,
                                                   lamp, r);
    }

    // 4. fan_in (HMMA 2-term A, plain B with k-wrap)
    convA2<<<S_TOT, 256>>>(xb, Axi, T_DIM);
    gemm_hmma<<<dim3(S_TOT / 128, D_DIM / 128), 256, HSMEM>>>(
        Axi, Bfi, fi_b, x, 2 * T_DIM, T_DIM, D_DIM, 2 * T_DIM / 64, T_DIM - 1);

    // 5. layernorm
    ln_kernel<<<S_TOT, 256>>>(x, ln_g, ln_b);

    // 6. logits (HMMA plain fp16 A, K=1024, 128x128 tile)
    conv_h<<<S_TOT, 256>>>(x, Ah);
    gemm_hmma<<<dim3(S_TOT / 128, V_DIM / 128), 256, HSMEM>>>(
        Ah, Bh, (const float*)0, out, 1024, 1024, V_DIM, 16, ~0);

    // 7. aux loss
    if (out_size > S_TOT * V_DIM) {
        aux_kernel<<<1, 256>>>(pcm, out + (size_t)S_TOT * V_DIM);
    }
}

// round 11
// speedup vs baseline: 1.6848x; 1.0024x over previous
#include <cuda_runtime.h>
#include <cuda_fp16.h>
#include <stdint.h>
#include <math.h>

// Problem dims
#define S_TOT 4096     // BS*N
#define D_DIM 1024
#define T_DIM 2048
#define V_DIM 32000
#define NB 8

// Scratch (device globals — allocation-free rule)
__device__ float g_x[S_TOT * D_DIM];
__device__ float g_xb[S_TOT * T_DIM];
__device__ float g_zhat[S_TOT * NB * 64];
__device__ float g_pcm[2 * S_TOT * NB];
__device__ __half g_Ah[(size_t)S_TOT * 1024];    // logits A plain fp16
__device__ __half g_Bh[(size_t)V_DIM * 1024];    // emb fp16
__device__ __half g_Axo[(size_t)S_TOT * 2048];   // fan_out A 2-term (hi|lo)
__device__ __half g_Bfo[(size_t)T_DIM * 1024];   // fo_w^T plain fp16
__device__ __half g_Axi[(size_t)S_TOT * 4096];   // fan_in A 2-term
__device__ __half g_Bfi[(size_t)D_DIM * 2048];   // fi_w^T plain fp16
__device__ __half g_W1p[NB * 256 * 64];
__device__ __half g_W2p[NB * 64 * 256];

__device__ __forceinline__ uint32_t smem_u32(const void* p) {
    uint32_t a;
    asm("{ .reg .u64 t; cvta.to.shared.u64 t, %1; cvt.u32.u64 %0, t; }"
        : "=r"(a) : "l"(p));
    return a;
}
__device__ __forceinline__ void ldsm4(uint32_t* r, uint32_t addr) {
    asm volatile("ldmatrix.sync.aligned.m8n8.x4.shared.b16 {%0,%1,%2,%3}, [%4];"
                 : "=r"(r[0]), "=r"(r[1]), "=r"(r[2]), "=r"(r[3]) : "r"(addr));
}
__device__ __forceinline__ void mma16816(float* c, const uint32_t* a,
                                         uint32_t b0, uint32_t b1) {
    asm volatile(
        "mma.sync.aligned.m16n8k16.row.col.f32.f16.f16.f32 "
        "{%0,%1,%2,%3}, {%4,%5,%6,%7}, {%8,%9}, {%0,%1,%2,%3};"
        : "+f"(c[0]), "+f"(c[1]), "+f"(c[2]), "+f"(c[3])
        : "r"(a[0]), "r"(a[1]), "r"(a[2]), "r"(a[3]), "r"(b0), "r"(b1));
}
__device__ __forceinline__ float gelu_f(float v) {
    float u = 0.7978845608028654f * (v + 0.044715f * v * v * v);
    float th;
    asm("tanh.approx.f32 %0, %1;" : "=f"(th) : "f"(u));
    return 0.5f * v * (1.0f + th);
}
__device__ __forceinline__ uint32_t pack_h2(float a, float b) {
    __half ha = __float2half_rn(a), hb = __float2half_rn(b);
    return (uint32_t)__half_as_ushort(ha) | ((uint32_t)__half_as_ushort(hb) << 16);
}

// ---------------------------------------------------------------------------
// Conversions
// ---------------------------------------------------------------------------
// plain fp16 copy (logits B): src f32 -> dst fp16, linear
__global__ void conv_h(const float* __restrict__ src, __half* __restrict__ dst) {
    size_t i = (size_t)blockIdx.x * 256 + threadIdx.x;
    float4 v = ((const float4*)src)[i];
    uint2 H;
    H.x = pack_h2(v.x, v.y); H.y = pack_h2(v.z, v.w);
    ((uint2*)dst)[i] = H;
}

// A 2-term (hi | lo): src [rows, K] f32 -> dst [rows, 2K] fp16 (fan_in A)
__global__ void convA2(const float* __restrict__ src, __half* __restrict__ dst,
                       int K) {
    int row = blockIdx.x;
    const float4* sp = (const float4*)(src + (size_t)row * K);
    __half* base = dst + (size_t)row * 2 * K;
    for (int q = threadIdx.x; q < K / 4; q += 256) {
        float4 v = sp[q];
        __half h0 = __float2half_rn(v.x), h1 = __float2half_rn(v.y);
        __half h2 = __float2half_rn(v.z), h3 = __float2half_rn(v.w);
        uint2 H, L;
        H.x = pack_h2(v.x, v.y); H.y = pack_h2(v.z, v.w);
        L.x = pack_h2(v.x - __half2float(h0), v.y - __half2float(h1));
        L.y = pack_h2(v.z - __half2float(h2), v.w - __half2float(h3));
        *(uint2*)(base + q * 4)     = H;
        *(uint2*)(base + K + q * 4) = L;
    }
}

// B transpose + plain fp16: src [K,N] row-major -> dst [N,K]
__global__ void convBT(const float* __restrict__ src, __half* __restrict__ dst,
                       int K, int N) {
    __shared__ float tile[32][33];
    int k0 = blockIdx.x * 32, n0 = blockIdx.y * 32;
    int tx = threadIdx.x & 31, ty = threadIdx.x >> 5;
    for (int i = ty; i < 32; i += 8)
        tile[i][tx] = src[(size_t)(k0 + i) * N + n0 + tx];
    __syncthreads();
    for (int i = ty; i < 32; i += 8) {
        int n = n0 + i;
        dst[(size_t)n * K + k0 + tx] = __float2half_rn(tile[tx][i]);
    }
}

// Pre-swizzled fp16 weights for mlp_tc
__global__ void convW1p(const float* __restrict__ W1, __half* __restrict__ W1p) {
    int idx = blockIdx.x * 256 + threadIdx.x;
    int t = idx >> 14, rem = idx & 16383;
    int rr = rem >> 6, ph = (rem >> 3) & 7, j = rem & 7;
    int k = ((ph ^ (rr & 7)) << 3) | j;
    W1p[idx] = __float2half_rn(W1[((size_t)t * 64 + k) * 256 + rr]);
}
__global__ void convW2p(const float* __restrict__ W2, __half* __restrict__ W2p) {
    int idx = blockIdx.x * 256 + threadIdx.x;
    int t = idx >> 14, rem = idx & 16383;
    int rr = rem >> 8, ph = (rem >> 3) & 31, j = rem & 7;
    int c = (ph & ~7) | ((ph & 7) ^ (rr & 7));
    int k = (c << 3) | j;
    W2p[idx] = __float2half_rn(W2[((size_t)t * 256 + k) * 64 + rr]);
}

// ---------------------------------------------------------------------------
// Embedding gather + pos add, fused with fan_out A 2-term split (hi|lo)
// ---------------------------------------------------------------------------
__global__ void embed_split(const int* __restrict__ ids,
                            const float* __restrict__ emb,
                            const float* __restrict__ pos,
                            __half* __restrict__ Axo) {
    int s = blockIdx.x;
    int q = threadIdx.x;  // float4 lane (0..255)
    int id = ids[s];
    float4 e = ((const float4*)(emb + (size_t)id * D_DIM))[q];
    float4 p = ((const float4*)(pos + (size_t)(s & 1023) * D_DIM))[q];
    float vx = e.x + p.x, vy = e.y + p.y, vz = e.z + p.z, vw = e.w + p.w;
    __half h0 = __float2half_rn(vx), h1 = __float2half_rn(vy);
    __half h2 = __float2half_rn(vz), h3 = __float2half_rn(vw);
    uint2 H, L;
    H.x = pack_h2(vx, vy); H.y = pack_h2(vz, vw);
    L.x = pack_h2(vx - __half2float(h0), vy - __half2float(h1));
    L.y = pack_h2(vz - __half2float(h2), vw - __half2float(h3));
    __half* base = Axo + (size_t)s * 2048 + q * 4;
    *(uint2*)base = H;
    *(uint2*)(base + 1024) = L;
}

// ---------------------------------------------------------------------------
// HMMA fp16 GEMM, 128x128 tile, 3-stage cp.async pipeline
// ---------------------------------------------------------------------------
#define HBUF 32768
#define HSMEM (3 * HBUF)

__global__ __launch_bounds__(256) void gemm_hmma(
    const __half* __restrict__ A, const __half* __restrict__ B,
    const float* __restrict__ bias, float* __restrict__ C,
    int ldA, int ldB, int N, int nch, int bkmask) {
    extern __shared__ __align__(128) char smem[];
    const uint32_t sb = smem_u32(smem);
    const int tid = threadIdx.x, lane = tid & 31, wid = tid >> 5;
    const int bm = blockIdx.x * 128, bn = blockIdx.y * 128;
    const int wm = (wid & 1) * 64, wn = (wid >> 1) * 32;

    float acc[4][4][4] = {};

    auto issue = [&](int ch, int buf) {
        int k0 = ch * 64;
        int bk = k0 & bkmask;
        uint32_t abase = sb + buf * HBUF;
        uint32_t bbase = abase + 16384;
#pragma unroll
        for (int i = 0; i < 4; i++) {
            int idx = tid + 256 * i;
            int r = idx >> 3, c = idx & 7;
            uint32_t off = (uint32_t)(r * 128 + ((c ^ (r & 7)) * 16));
            const __half* gp = A + (size_t)(bm + r) * ldA + k0 + c * 8;
            asm volatile("cp.async.cg.shared.global [%0], [%1], 16;"
                         :: "r"(abase + off), "l"(gp));
        }
#pragma unroll
        for (int i = 0; i < 4; i++) {
            int idx = tid + 256 * i;
            int r = idx >> 3, c = idx & 7;
            uint32_t off = (uint32_t)(r * 128 + ((c ^ (r & 7)) * 16));
            const __half* gp = B + (size_t)(bn + r) * ldB + bk + c * 8;
            asm volatile("cp.async.cg.shared.global [%0], [%1], 16;"
                         :: "r"(bbase + off), "l"(gp));
        }
        asm volatile("cp.async.commit_group;" ::: "memory");
    };

    // Prologue: prefetch chunks 0 and 1
    issue(0, 0);
    issue(1, 1);

    int buf = 0;
    for (int ch = 0; ch < nch; ch++) {
        // Wait for chunk ch: allow 1 pending group if ch+1 was issued, else 0
        if (ch + 1 < nch) {
            asm volatile("cp.async.wait_group 1;" ::: "memory");
        } else {
            asm volatile("cp.async.wait_group 0;" ::: "memory");
        }
        __syncthreads();  // chunk ch visible; buffer (ch-1)%3 reads all done
        if (ch + 2 < nch) {
            int nb = buf + 2;
            if (nb >= 3) nb -= 3;
            issue(ch + 2, nb);
        }

        uint32_t abase = sb + buf * HBUF;
        uint32_t bbase = abase + 16384;
#pragma unroll
        for (int ks = 0; ks < 4; ks++) {
            uint32_t afr[4][4];
#pragma unroll
            for (int mi = 0; mi < 4; mi++) {
                int r = wm + mi * 16 + (lane & 15);
                int cu = ks * 2 + (lane >> 4);
                uint32_t addr = abase + r * 128 + ((cu ^ (r & 7)) * 16);
                ldsm4(afr[mi], addr);
            }
            uint32_t bfr[2][4];
#pragma unroll
            for (int p = 0; p < 2; p++) {
                int r = wn + p * 16 + (lane & 7) + ((lane >> 4) * 8);
                int cu = ks * 2 + ((lane >> 3) & 1);
                uint32_t addr = bbase + r * 128 + ((cu ^ (r & 7)) * 16);
                ldsm4(bfr[p], addr);
            }
#pragma unroll
            for (int mi = 0; mi < 4; mi++)
#pragma unroll
                for (int nj = 0; nj < 4; nj++)
                    mma16816(acc[mi][nj], afr[mi],
                             bfr[nj >> 1][(nj & 1) * 2 + 0],
                             bfr[nj >> 1][(nj & 1) * 2 + 1]);
        }
        if (++buf == 3) buf = 0;
    }

#pragma unroll
    for (int mi = 0; mi < 4; mi++) {
#pragma unroll
        for (int nj = 0; nj < 4; nj++) {
            int row = bm + wm + mi * 16 + (lane >> 2);
            int col = bn + wn + nj * 8 + (lane & 3) * 2;
            float b0 = bias ? bias[col] : 0.0f;
            float b1 = bias ? bias[col + 1] : 0.0f;
            float2 v0 = make_float2(acc[mi][nj][0] + b0, acc[mi][nj][1] + b1);
            float2 v1 = make_float2(acc[mi][nj][2] + b0, acc[mi][nj][3] + b1);
            *(float2*)(C + (size_t)row * N + col) = v0;
            *(float2*)(C + (size_t)(row + 8) * N + col) = v1;
        }
    }
}

// ---------------------------------------------------------------------------
// Fused HMMA refine MLP + z-pass. Phase2 uses PLAIN fp16 H (K'=256).
// ---------------------------------------------------------------------------
#define MLPTC_SMEM (122880)
__global__ __launch_bounds__(256) void mlp_tc(
    float* __restrict__ xb, const __half* __restrict__ W1p,
    const __half* __restrict__ W2p, const float* __restrict__ Wz,
    float* __restrict__ zhat, float* __restrict__ pcm,
    const float* __restrict__ lam_logit, int r) {
    extern __shared__ __align__(128) char smem[];
    const uint32_t sb = smem_u32(smem);
    const uint32_t XS = sb, W1S = sb + 32768, HS = sb, W2S = sb + 65536;
    const uint32_t WZS = sb + 98304;
    float* wzsp = (float*)(smem + 98304);
    float* zsp = (float*)(smem + 114688);
    const int tid = threadIdx.x, lane = tid & 31, wid = tid >> 5;
    const int t = blockIdx.y, rt = blockIdx.x;
    const int wm = (wid & 1) * 64;
    float lam = 1.0f;
    if (r > 0) lam = 1.0f / (1.0f + expf(-lam_logit[0]));

    // async-load weights: W1p, W2p (pre-swizzled fp16), Wz (fp32)
    {
        const __half* w1g = W1p + (size_t)t * 16384;
        const __half* w2g = W2p + (size_t)t * 16384;
        const float* wzg = Wz + (size_t)t * 4096;
#pragma unroll
        for (int i = 0; i < 8; i++) {
            int idx = tid + 256 * i;
            asm volatile("cp.async.cg.shared.global [%0], [%1], 16;"
                         :: "r"(W1S + idx * 16), "l"(w1g + idx * 8));
        }
#pragma unroll
        for (int i = 0; i < 8; i++) {
            int idx = tid + 256 * i;
            asm volatile("cp.async.cg.shared.global [%0], [%1], 16;"
                         :: "r"(W2S + idx * 16), "l"(w2g + idx * 8));
        }
#pragma unroll
        for (int i = 0; i < 4; i++) {
            int idx = tid + 256 * i;
            asm volatile("cp.async.cg.shared.global [%0], [%1], 16;"
                         :: "r"(WZS + idx * 16), "l"(wzg + idx * 4));
        }
        asm volatile("cp.async.commit_group;" ::: "memory");
    }

    // X tile: load fp32, split hi/lo fp16 into XS (row stride 256B, swizzled)
#pragma unroll
    for (int i = 0; i < 4; i++) {
        int idx = tid + 256 * i;
        int lr = idx >> 3, c = idx & 7;
        int g = rt * 128 + lr;
        const float* xp = xb + ((size_t)(g >> 2) * 32 + t * 4 + (g & 3)) * 64 + c * 8;
        float4 v0 = *(const float4*)xp;
        float4 v1 = *(const float4*)(xp + 4);
        float vv[8] = {v0.x, v0.y, v0.z, v0.w, v1.x, v1.y, v1.z, v1.w};
        uint4 Hh, Ll;
        uint32_t* hw = (uint32_t*)&Hh;
        uint32_t* lw = (uint32_t*)&Ll;
#pragma unroll
        for (int j = 0; j < 4; j++) {
            float a = vv[2 * j], b = vv[2 * j + 1];
            __half ha = __float2half_rn(a), hb = __float2half_rn(b);
            hw[j] = (uint32_t)__half_as_ushort(ha) |
                    ((uint32_t)__half_as_ushort(hb) << 16);
            lw[j] = pack_h2(a - __half2float(ha), b - __half2float(hb));
        }
        int phh = c ^ (lr & 7);
        *(uint4*)(smem + lr * 256 + phh * 16) = Hh;
        *(uint4*)(smem + lr * 256 + (8 + phh) * 16) = Ll;
    }
    __syncthreads();  // XS visible

    // z = mean_c (hi+lo reconstruction ~fp32-exact)
    {
        int s_loc = tid >> 3;
        int d0 = (tid & 7) * 8;
        float zv[8] = {};
#pragma unroll
        for (int c = 0; c < 4; c++) {
            int lr = s_loc * 4 + c;
            int byte_off = lr * 256 + (((d0 >> 3) ^ (lr & 7)) * 16);
            uint4 hi = *(const uint4*)(smem + byte_off);
            uint4 lo = *(const uint4*)(smem + byte_off + 128);
            const __half2* hp = (const __half2*)&hi;
            const __half2* lp = (const __half2*)&lo;
#pragma unroll
            for (int j = 0; j < 4; j++) {
                float2 h2 = __half22float2(hp[j]);
                float2 l2 = __half22float2(lp[j]);
                zv[2 * j]     += h2.x + l2.x;
                zv[2 * j + 1] += h2.y + l2.y;
            }
        }
#pragma unroll
        for (int j = 0; j < 8; j++) zsp[s_loc * 64 + d0 + j] = 0.25f * zv[j];
    }
    asm volatile("cp.async.wait_group 0;" ::: "memory");  // weights in
    __syncthreads();  // ZS + weights visible

    // pcm (r>0) + zhat = z @ Wz[t]
    {
        int s_loc = tid >> 3, e0 = (tid & 7) * 8;
        int st = (rt * 32 + s_loc) * 8 + t;
        const float* zr = zsp + s_loc * 64;
        float acc[8] = {};
        for (int d = 0; d < 64; d++) {
            float zv = zr[d];
            const float* wr = wzsp + d * 64 + e0;
#pragma unroll
            for (int j = 0; j < 8; j++) acc[j] = fmaf(zv, wr[j], acc[j]);
        }
        if (r > 0) {
            float sq = 0.0f;
#pragma unroll
            for (int j = 0; j < 8; j++) {
                float diff = zhat[(size_t)st * 64 + e0 + j] - zr[e0 + j];
                sq = fmaf(diff, diff, sq);
            }
            sq += __shfl_down_sync(0xffffffffu, sq, 4, 8);
            sq += __shfl_down_sync(0xffffffffu, sq, 2, 8);
            sq += __shfl_down_sync(0xffffffffu, sq, 1, 8);
            if ((tid & 7) == 0)
                pcm[(size_t)(r - 1) * (S_TOT * NB) + st] = sq;
        }
#pragma unroll
        for (int j = 0; j < 8; j++) zhat[(size_t)st * 64 + e0 + j] = acc[j];
    }

    // Phase 1: H[128x256] = gelu(X2 @ W1h), warp tile 64x64
    float acc1[4][8][4] = {};
    {
        const int wn1 = (wid >> 1) * 64;
#pragma unroll
        for (int ks = 0; ks < 8; ks++) {
            uint32_t afr[4][4];
#pragma unroll
            for (int mi = 0; mi < 4; mi++) {
                int rr = wm + mi * 16 + (lane & 15);
                int cu = ks * 2 + (lane >> 4);
                int ph = (cu & 8) | ((cu & 7) ^ (rr & 7));
                ldsm4(afr[mi], XS + rr * 256 + ph * 16);
            }
            uint32_t bfr[4][4];
#pragma unroll
            for (int p = 0; p < 4; p++) {
                int rr = wn1 + p * 16 + (lane & 7) + ((lane >> 4) * 8);
                int cu = (ks * 2 + ((lane >> 3) & 1)) & 7;
                int ph = cu ^ (rr & 7);
                ldsm4(bfr[p], W1S + rr * 128 + ph * 16);
            }
#pragma unroll
            for (int mi = 0; mi < 4; mi++)
#pragma unroll
                for (int nj = 0; nj < 8; nj++)
                    mma16816(acc1[mi][nj], afr[mi],
                             bfr[nj >> 1][(nj & 1) * 2 + 0],
                             bfr[nj >> 1][(nj & 1) * 2 + 1]);
        }
        __syncthreads();  // phase1 smem reads done (XS/W1S free)

        // gelu + PLAIN fp16 store into HS (row stride 512B)
        const int wn1b = (wid >> 1) * 64;
#pragma unroll
        for (int mi = 0; mi < 4; mi++)
#pragma unroll
            for (int nj = 0; nj < 8; nj++) {
                int r0 = wm + mi * 16 + (lane >> 2);
                int n0 = wn1b + nj * 8 + (lane & 3) * 2;
                float g0 = gelu_f(acc1[mi][nj][0]);
                float g1 = gelu_f(acc1[mi][nj][1]);
                float g2 = gelu_f(acc1[mi][nj][2]);
                float g3 = gelu_f(acc1[mi][nj][3]);
                uint32_t hi0 = pack_h2(g0, g1);
                uint32_t hi1 = pack_h2(g2, g3);
                int ch = n0 >> 3, within = (n0 & 7) * 2;
                int ph0 = (ch & ~7) | ((ch & 7) ^ (r0 & 7));
                int ph1 = (ch & ~7) | ((ch & 7) ^ ((r0 + 8) & 7));
                *(uint32_t*)(smem + r0 * 512 + ph0 * 16 + within) = hi0;
                *(uint32_t*)(smem + (r0 + 8) * 512 + ph1 * 16 + within) = hi1;
            }
    }
    __syncthreads();

    // Phase 2: delta[128x64] = H @ W2h, warp tile 64x16, K'=256
    float acc2[4][2][4] = {};
    const int wn2 = (wid >> 1) * 16;
#pragma unroll
    for (int ks = 0; ks < 16; ks++) {
        uint32_t afr[4][4];
#pragma unroll
        for (int mi = 0; mi < 4; mi++) {
            int rr = wm + mi * 16 + (lane & 15);
            int cu = ks * 2 + (lane >> 4);
            int ph = (cu & ~7) | ((cu & 7) ^ (rr & 7));
            ldsm4(afr[mi], HS + rr * 512 + ph * 16);
        }
        uint32_t bfr[4];
        {
            int rr = wn2 + (lane & 7) + ((lane >> 4) * 8);
            int cu = ks * 2 + ((lane >> 3) & 1);
            int ph = (cu & ~7) | ((cu & 7) ^ (rr & 7));
            ldsm4(bfr, W2S + rr * 512 + ph * 16);
        }
#pragma unroll
        for (int mi = 0; mi < 4; mi++)
#pragma unroll
            for (int nj = 0; nj < 2; nj++)
                mma16816(acc2[mi][nj], afr[mi], bfr[nj * 2], bfr[nj * 2 + 1]);
    }

    // Epilogue: xb += lam * delta
#pragma unroll
    for (int mi = 0; mi < 4; mi++)
#pragma unroll
        for (int nj = 0; nj < 2; nj++) {
            int r0 = wm + mi * 16 + (lane >> 2);
            int n0 = wn2 + nj * 8 + (lane & 3) * 2;
#pragma unroll
            for (int h = 0; h < 2; h++) {
                int g = rt * 128 + r0 + h * 8;
                float* p = xb + ((size_t)(g >> 2) * 32 + t * 4 + (g & 3)) * 64 + n0;
                float2 old = *(float2*)p;
                old.x += lam * acc2[mi][nj][h * 2 + 0];
                old.y += lam * acc2[mi][nj][h * 2 + 1];
                *(float2*)p = old;
            }
        }
}

// ---------------------------------------------------------------------------
// LayerNorm fused with fp16 conversion: reads x fp32, writes Ah fp16
// ---------------------------------------------------------------------------
__global__ void ln_kernel(const float* __restrict__ x,
                          const float* __restrict__ g,
                          const float* __restrict__ b,
                          __half* __restrict__ Ah) {
    __shared__ float red[256];
    const int s = blockIdx.x, tid = threadIdx.x;
    const float4* row = (const float4*)(x + (size_t)s * D_DIM);
    float4 v = row[tid];
    red[tid] = v.x + v.y + v.z + v.w;
    __syncthreads();
    for (int o = 128; o > 0; o >>= 1) {
        if (tid < o) red[tid] += red[tid + o];
        __syncthreads();
    }
    float mu = red[0] * (1.0f / 1024.0f);
    __syncthreads();
    float dx = v.x - mu, dy = v.y - mu, dz = v.z - mu, dw = v.w - mu;
    red[tid] = dx * dx + dy * dy + dz * dz + dw * dw;
    __syncthreads();
    for (int o = 128; o > 0; o >>= 1) {
        if (tid < o) red[tid] += red[tid + o];
        __syncthreads();
    }
    float rstd = rsqrtf(red[0] * (1.0f / 1024.0f) + 1e-5f);
    float4 gg = ((const float4*)g)[tid];
    float4 bb = ((const float4*)b)[tid];
    float ox = dx * rstd * gg.x + bb.x;
    float oy = dy * rstd * gg.y + bb.y;
    float oz = dz * rstd * gg.z + bb.z;
    float ow = dw * rstd * gg.w + bb.w;
    uint2 H;
    H.x = pack_h2(ox, oy);
    H.y = pack_h2(oz, ow);
    ((uint2*)(Ah + (size_t)s * D_DIM))[tid] = H;
}

// ---------------------------------------------------------------------------
// Deterministic aux reduction
// ---------------------------------------------------------------------------
__global__ void aux_kernel(const float* __restrict__ pcm, float* __restrict__ out) {
    __shared__ float red[256];
    const int tid = threadIdx.x;
    float s = 0.0f;
    for (int i = tid; i < 2 * S_TOT * NB; i += 256) s += pcm[i];
    red[tid] = s;
    __syncthreads();
    for (int o = 128; o > 0; o >>= 1) {
        if (tid < o) red[tid] += red[tid + o];
        __syncthreads();
    }
    if (tid == 0) out[0] = 0.1f * red[0] / 262144.0f;
}

// ---------------------------------------------------------------------------
extern "C" void kernel_launch(void* const* d_in, const int* in_sizes, int n_in,
                              void* d_out, int out_size) {
    const int*   ids  = (const int*)d_in[0];
    const float* emb  = (const float*)d_in[1];
    const float* pos  = (const float*)d_in[2];
    const float* fo_w = (const float*)d_in[3];
    const float* fo_b = (const float*)d_in[4];
    const float* W1   = (const float*)d_in[5];
    const float* W2   = (const float*)d_in[6];
    const float* Wz   = (const float*)d_in[7];
    const float* fi_w = (const float*)d_in[8];
    const float* fi_b = (const float*)d_in[9];
    const float* ln_g = (const float*)d_in[10];
    const float* ln_b = (const float*)d_in[11];
    const float* lamp = (const float*)d_in[12];
    float* out = (float*)d_out;

    float *x, *xb, *zhat, *pcm;
    __half *Ah, *Bh, *Axo, *Bfo, *Axi, *Bfi, *W1p, *W2p;
    cudaGetSymbolAddress((void**)&x,    g_x);
    cudaGetSymbolAddress((void**)&xb,   g_xb);
    cudaGetSymbolAddress((void**)&zhat, g_zhat);
    cudaGetSymbolAddress((void**)&pcm,  g_pcm);
    cudaGetSymbolAddress((void**)&Ah,   g_Ah);
    cudaGetSymbolAddress((void**)&Bh,   g_Bh);
    cudaGetSymbolAddress((void**)&Axo,  g_Axo);
    cudaGetSymbolAddress((void**)&Bfo,  g_Bfo);
    cudaGetSymbolAddress((void**)&Axi,  g_Axi);
    cudaGetSymbolAddress((void**)&Bfi,  g_Bfi);
    cudaGetSymbolAddress((void**)&W1p,  g_W1p);
    cudaGetSymbolAddress((void**)&W2p,  g_W2p);

    cudaFuncSetAttribute(gemm_hmma, cudaFuncAttributeMaxDynamicSharedMemorySize,
                         HSMEM);
    cudaFuncSetAttribute(mlp_tc, cudaFuncAttributeMaxDynamicSharedMemorySize,
                         MLPTC_SMEM);

    // 1. embed (fused fan_out A-split) + weight conversions
    embed_split<<<S_TOT, 256>>>(ids, emb, pos, Axo);
    conv_h<<<V_DIM, 256>>>(emb, Bh);
    convBT<<<dim3(D_DIM / 32, T_DIM / 32), 256>>>(fo_w, Bfo, D_DIM, T_DIM);
    convBT<<<dim3(T_DIM / 32, D_DIM / 32), 256>>>(fi_w, Bfi, T_DIM, D_DIM);
    convW1p<<<512, 256>>>(W1, W1p);
    convW2p<<<512, 256>>>(W2, W2p);

    // 2. fan_out (HMMA 2-term A, plain B with k-wrap)
    gemm_hmma<<<dim3(S_TOT / 128, T_DIM / 128), 256, HSMEM>>>(
        Axo, Bfo, fo_b, xb, 2 * D_DIM, D_DIM, T_DIM, 2 * D_DIM / 64, D_DIM - 1);

    // 3. refine passes (fused z-pass + MLP on tensor cores)
    for (int r = 0; r < 3; r++) {
        mlp_tc<<<dim3(128, NB), 256, MLPTC_SMEM>>>(xb, W1p, W2p, Wz, zhat, pcm,
                                                   lamp, r);
    }

    // 4. fan_in (HMMA 2-term A, plain B with k-wrap)
    convA2<<<S_TOT, 256>>>(xb, Axi, T_DIM);
    gemm_hmma<<<dim3(S_TOT / 128, D_DIM / 128), 256, HSMEM>>>(
        Axi, Bfi, fi_b, x, 2 * T_DIM, T_DIM, D_DIM, 2 * T_DIM / 64, T_DIM - 1);

    // 5. layernorm (fused fp16 output for logits A)
    ln_kernel<<<S_TOT, 256>>>(x, ln_g, ln_b, Ah);

    // 6. logits (HMMA plain fp16 A, K=1024, 128x128 tile)
    gemm_hmma<<<dim3(S_TOT / 128, V_DIM / 128), 256, HSMEM>>>(
        Ah, Bh, (const float*)0, out, 1024, 1024, V_DIM, 16, ~0);

    // 7. aux loss
    if (out_size > S_TOT * V_DIM) {
        aux_kernel<<<1, 256>>>(pcm, out + (size_t)S_TOT * V_DIM);
    }
}